// round 3
// baseline (speedup 1.0000x reference)
#include <cuda_runtime.h>

#define NN 512
#define DD 128
#define HH 128
#define PP (NN*NN)
#define EPSV 1e-6f

// ---------------- scratch (static device allocations; no cudaMalloc) ----------------
// g_xn is reused as the einsum output buffer (strictly sequential use):
//   K1 writes g_xn -> K2 reads g_xn, writes leftT/rightT/ogT -> K3 writes g_xn (as outT)
//   -> K4 reads g_xn (as outT) + ogT.
__device__ float g_xn[(size_t)PP * DD];      // [p][d], later reused as outT [d][i*N+j]
__device__ float g_leftT[(size_t)HH * PP];   // [d][k*N+i]
__device__ float g_rightT[(size_t)HH * PP];  // [d][k*N+j]
__device__ float g_ogT[(size_t)HH * PP];     // [d][p]

__device__ __forceinline__ float sigmoidf_(float x) {
    return 1.0f / (1.0f + expf(-x));
}

// ---------------- K1: layernorm over D=128, warp per row ----------------
__global__ void ln_kernel(const float* __restrict__ x,
                          const float* __restrict__ scale,
                          const float* __restrict__ bias) {
    int row = blockIdx.x * 8 + threadIdx.y;
    int lane = threadIdx.x;
    float4 v = reinterpret_cast<const float4*>(x + (size_t)row * DD)[lane];
    float s  = v.x + v.y + v.z + v.w;
    float sq = v.x*v.x + v.y*v.y + v.z*v.z + v.w*v.w;
    #pragma unroll
    for (int o = 16; o > 0; o >>= 1) {
        s  += __shfl_xor_sync(0xffffffffu, s, o);
        sq += __shfl_xor_sync(0xffffffffu, sq, o);
    }
    float mu = s * (1.0f / DD);
    float var = sq * (1.0f / DD) - mu * mu;
    float rstd = rsqrtf(var + EPSV);
    float4 sc = reinterpret_cast<const float4*>(scale)[lane];
    float4 bi = reinterpret_cast<const float4*>(bias)[lane];
    float4 o4;
    o4.x = (v.x - mu) * rstd * sc.x + bi.x;
    o4.y = (v.y - mu) * rstd * sc.y + bi.y;
    o4.z = (v.z - mu) * rstd * sc.z + bi.z;
    o4.w = (v.w - mu) * rstd * sc.w + bi.w;
    reinterpret_cast<float4*>(g_xn + (size_t)row * DD)[lane] = o4;
}

// ---------------- K2: fused 5-way projection + mask + gating ----------------
// Block: 64 rows (p) x 32 cols (h), all 5 weight matrices simultaneously.
// Epilogue transposes through shared so left/right/og are written d-major, coalesced.
__global__ __launch_bounds__(256) void proj_kernel(
    const float* __restrict__ src_mask,
    const float* __restrict__ Wl,  const float* __restrict__ bl,
    const float* __restrict__ Wr,  const float* __restrict__ br,
    const float* __restrict__ Wlg, const float* __restrict__ blg,
    const float* __restrict__ Wrg, const float* __restrict__ brg,
    const float* __restrict__ Wog, const float* __restrict__ bog)
{
    __shared__ __align__(16) float xs[128 * 68];    // [k][r], pitch 68
    __shared__ __align__(16) float ws[5 * 16 * 34]; // [m][k][c], pitch 34; reused as stage
    int tid = threadIdx.x;
    int tx = tid & 15, ty = tid >> 4;
    int p0 = blockIdx.x * 64, h0 = blockIdx.y * 32;

    // load x tile transposed into shared: xs[k][r]
    for (int t = tid; t < 64 * 32; t += 256) {
        int r = t >> 5, k4 = t & 31;
        float4 v = *reinterpret_cast<const float4*>(g_xn + (size_t)(p0 + r) * DD + k4 * 4);
        xs[(k4*4 + 0)*68 + r] = v.x;
        xs[(k4*4 + 1)*68 + r] = v.y;
        xs[(k4*4 + 2)*68 + r] = v.z;
        xs[(k4*4 + 3)*68 + r] = v.w;
    }

    const float* Wm[5] = {Wl, Wr, Wlg, Wrg, Wog};
    float acc[5][4][2] = {};

    int lc = tid & 31, lk = tid >> 5;  // lk: 0..7
    for (int kk = 0; kk < 128; kk += 16) {
        __syncthreads();
        #pragma unroll
        for (int m = 0; m < 5; m++) {
            ws[(m*16 + lk    )*34 + lc] = Wm[m][(kk + lk    ) * HH + h0 + lc];
            ws[(m*16 + lk + 8)*34 + lc] = Wm[m][(kk + lk + 8) * HH + h0 + lc];
        }
        __syncthreads();
        #pragma unroll
        for (int k = 0; k < 16; k++) {
            float4 a = *reinterpret_cast<const float4*>(&xs[(kk + k)*68 + tx*4]);
            float av[4] = {a.x, a.y, a.z, a.w};
            #pragma unroll
            for (int m = 0; m < 5; m++) {
                float2 w = *reinterpret_cast<const float2*>(&ws[(m*16 + k)*34 + ty*2]);
                #pragma unroll
                for (int rr = 0; rr < 4; rr++) {
                    acc[m][rr][0] += av[rr] * w.x;
                    acc[m][rr][1] += av[rr] * w.y;
                }
            }
        }
    }

    // epilogue: bias + mask + sigmoid gating
    float mval[4];
    #pragma unroll
    for (int rr = 0; rr < 4; rr++) {
        int p = p0 + tx*4 + rr;
        mval[rr] = src_mask[p >> 9] * src_mask[p & (NN - 1)];
    }
    float Lv[4][2], Rv[4][2], Gv[4][2];
    #pragma unroll
    for (int cc = 0; cc < 2; cc++) {
        int h = h0 + ty*2 + cc;
        float bL = bl[h], bR = br[h], bLG = blg[h], bRG = brg[h], bOG = bog[h];
        #pragma unroll
        for (int rr = 0; rr < 4; rr++) {
            Lv[rr][cc] = (acc[0][rr][cc] + bL) * mval[rr] * sigmoidf_(acc[2][rr][cc] + bLG);
            Rv[rr][cc] = (acc[1][rr][cc] + bR) * mval[rr] * sigmoidf_(acc[3][rr][cc] + bRG);
            Gv[rr][cc] = sigmoidf_(acc[4][rr][cc] + bOG);
        }
    }

    // staged transposed writes (d-major), coalesced. stage[c][r], pitch 68; fits in ws.
    float* stage = ws;
    float* dsts[3] = {g_leftT, g_rightT, g_ogT};
    for (int which = 0; which < 3; which++) {
        __syncthreads();
        #pragma unroll
        for (int cc = 0; cc < 2; cc++)
            #pragma unroll
            for (int rr = 0; rr < 4; rr++) {
                float v = (which == 0) ? Lv[rr][cc] : (which == 1) ? Rv[rr][cc] : Gv[rr][cc];
                stage[(ty*2 + cc)*68 + tx*4 + rr] = v;
            }
        __syncthreads();
        float* dst = dsts[which];
        for (int t = tid; t < 32 * 64; t += 256) {
            int c = t >> 6, r = t & 63;
            dst[(size_t)(h0 + c) * PP + p0 + r] = stage[c*68 + r];
        }
    }
}

// ---------------- K3: triangle einsum = 128 batched SGEMMs (K-major A and B) ----------------
// out[d][i][j] = sum_k leftT[d][k][i] * rightT[d][k][j]
// 128x128 tile, 8x8 per thread: 64 FMA per 16 LDS-floats -> FMA-bound, not LDS-bound.
__global__ __launch_bounds__(256) void einsum_kernel() {
    __shared__ __align__(16) float As[16 * 132];
    __shared__ __align__(16) float Bs[16 * 132];
    int tid = threadIdx.x;
    int tx = tid & 15, ty = tid >> 4;
    int j0 = blockIdx.x * 128, i0 = blockIdx.y * 128, d = blockIdx.z;
    const float* L = g_leftT  + (size_t)d * PP;
    const float* R = g_rightT + (size_t)d * PP;
    float acc[8][8] = {};
    int li = tid & 31, lk = tid >> 5;  // li: float4 col 0..31, lk: row 0..7
    for (int kk = 0; kk < NN; kk += 16) {
        __syncthreads();
        #pragma unroll
        for (int q = 0; q < 2; q++) {
            *reinterpret_cast<float4*>(&As[(lk + q*8)*132 + li*4]) =
                *reinterpret_cast<const float4*>(&L[(size_t)(kk + lk + q*8) * NN + i0 + li*4]);
            *reinterpret_cast<float4*>(&Bs[(lk + q*8)*132 + li*4]) =
                *reinterpret_cast<const float4*>(&R[(size_t)(kk + lk + q*8) * NN + j0 + li*4]);
        }
        __syncthreads();
        #pragma unroll
        for (int k = 0; k < 16; k++) {
            float a[8], b[8];
            *reinterpret_cast<float4*>(&a[0]) = *reinterpret_cast<const float4*>(&As[k*132 + ty*8]);
            *reinterpret_cast<float4*>(&a[4]) = *reinterpret_cast<const float4*>(&As[k*132 + ty*8 + 4]);
            *reinterpret_cast<float4*>(&b[0]) = *reinterpret_cast<const float4*>(&Bs[k*132 + tx*8]);
            *reinterpret_cast<float4*>(&b[4]) = *reinterpret_cast<const float4*>(&Bs[k*132 + tx*8 + 4]);
            #pragma unroll
            for (int rr = 0; rr < 8; rr++)
                #pragma unroll
                for (int cc = 0; cc < 8; cc++)
                    acc[rr][cc] += a[rr] * b[cc];
        }
    }
    float* O = g_xn + (size_t)d * PP;   // reuse g_xn as outT
    #pragma unroll
    for (int rr = 0; rr < 8; rr++) {
        size_t base = (size_t)(i0 + ty*8 + rr) * NN + j0 + tx*8;
        *reinterpret_cast<float4*>(&O[base]) =
            make_float4(acc[rr][0], acc[rr][1], acc[rr][2], acc[rr][3]);
        *reinterpret_cast<float4*>(&O[base + 4]) =
            make_float4(acc[rr][4], acc[rr][5], acc[rr][6], acc[rr][7]);
    }
}

// ---------------- K4: out-layernorm * ogate, then @ W_out + b_out ----------------
// Block: 64 rows (p). Transpose outT slab into shared, LN over d, gate, then GEMM.
__global__ __launch_bounds__(256) void out_kernel(
    const float* __restrict__ onscale, const float* __restrict__ onbias,
    const float* __restrict__ Wout,    const float* __restrict__ bout,
    float* __restrict__ out)
{
    __shared__ __align__(16) float sh[128 * 68];   // [d][r]
    __shared__ __align__(16) float wsh[16 * 132];  // [k][c]
    __shared__ float red_s[4][64];
    __shared__ float red_q[4][64];
    int tid = threadIdx.x;
    int p0 = blockIdx.x * 64;
    const float* outT = g_xn;   // einsum result lives in g_xn

    for (int t = tid; t < 128 * 64; t += 256) {
        int dd = t >> 6, r = t & 63;
        sh[dd*68 + r] = outT[(size_t)dd * PP + p0 + r];
    }
    __syncthreads();

    int r = tid & 63, q = tid >> 6;
    float s = 0.f, sq = 0.f;
    #pragma unroll
    for (int u = 0; u < 32; u++) {
        float v = sh[(q*32 + u)*68 + r];
        s += v; sq += v*v;
    }
    red_s[q][r] = s; red_q[q][r] = sq;
    __syncthreads();
    float st  = red_s[0][r] + red_s[1][r] + red_s[2][r] + red_s[3][r];
    float sqt = red_q[0][r] + red_q[1][r] + red_q[2][r] + red_q[3][r];
    float mu = st * (1.0f / HH);
    float rstd = rsqrtf(sqt * (1.0f / HH) - mu*mu + EPSV);
    #pragma unroll
    for (int u = 0; u < 32; u++) {
        int dd = q*32 + u;
        float v = sh[dd*68 + r];
        float g = g_ogT[(size_t)dd * PP + p0 + r];
        sh[dd*68 + r] = ((v - mu) * rstd * onscale[dd] + onbias[dd]) * g;
    }

    // GEMM: out[p][c] = sum_d sh[d][p] * Wout[d][c] + bout[c]
    int tx = tid & 15, ty = tid >> 4;   // rows tx*4.., cols ty*8..
    float acc[4][8] = {};
    int lc = tid & 127, lk2 = tid >> 7;  // lk2: 0..1
    for (int kk = 0; kk < 128; kk += 16) {
        __syncthreads();
        #pragma unroll
        for (int qq = 0; qq < 8; qq++)
            wsh[(lk2 + qq*2)*132 + lc] = Wout[(size_t)(kk + lk2 + qq*2) * DD + lc];
        __syncthreads();
        #pragma unroll
        for (int k = 0; k < 16; k++) {
            float4 a  = *reinterpret_cast<const float4*>(&sh[(kk + k)*68 + tx*4]);
            float4 w0 = *reinterpret_cast<const float4*>(&wsh[k*132 + ty*8]);
            float4 w1 = *reinterpret_cast<const float4*>(&wsh[k*132 + ty*8 + 4]);
            float av[4] = {a.x, a.y, a.z, a.w};
            float wv[8] = {w0.x, w0.y, w0.z, w0.w, w1.x, w1.y, w1.z, w1.w};
            #pragma unroll
            for (int rr = 0; rr < 4; rr++)
                #pragma unroll
                for (int cc = 0; cc < 8; cc++)
                    acc[rr][cc] += av[rr] * wv[cc];
        }
    }
    float4 bb0 = *reinterpret_cast<const float4*>(&bout[ty*8]);
    float4 bb1 = *reinterpret_cast<const float4*>(&bout[ty*8 + 4]);
    #pragma unroll
    for (int rr = 0; rr < 4; rr++) {
        size_t base = (size_t)(p0 + tx*4 + rr) * DD + ty*8;
        float4 o0 = make_float4(acc[rr][0] + bb0.x, acc[rr][1] + bb0.y,
                                acc[rr][2] + bb0.z, acc[rr][3] + bb0.w);
        float4 o1 = make_float4(acc[rr][4] + bb1.x, acc[rr][5] + bb1.y,
                                acc[rr][6] + bb1.z, acc[rr][7] + bb1.w);
        *reinterpret_cast<float4*>(&out[base])     = o0;
        *reinterpret_cast<float4*>(&out[base + 4]) = o1;
    }
}

// ---------------- launch ----------------
extern "C" void kernel_launch(void* const* d_in, const int* in_sizes, int n_in,
                              void* d_out, int out_size) {
    const float* x        = (const float*)d_in[0];
    const float* src_mask = (const float*)d_in[1];
    const float* nscale   = (const float*)d_in[2];
    const float* nbias    = (const float*)d_in[3];
    const float* Wl       = (const float*)d_in[4];
    const float* bl       = (const float*)d_in[5];
    const float* Wr       = (const float*)d_in[6];
    const float* br       = (const float*)d_in[7];
    const float* Wlg      = (const float*)d_in[8];
    const float* blg      = (const float*)d_in[9];
    const float* Wrg      = (const float*)d_in[10];
    const float* brg      = (const float*)d_in[11];
    const float* Wog      = (const float*)d_in[12];
    const float* bog      = (const float*)d_in[13];
    const float* onscale  = (const float*)d_in[14];
    const float* onbias   = (const float*)d_in[15];
    const float* Wout     = (const float*)d_in[16];
    const float* bout     = (const float*)d_in[17];
    float* out = (float*)d_out;

    ln_kernel<<<PP / 8, dim3(32, 8)>>>(x, nscale, nbias);
    proj_kernel<<<dim3(PP / 64, HH / 32), 256>>>(src_mask, Wl, bl, Wr, br,
                                                 Wlg, blg, Wrg, brg, Wog, bog);
    einsum_kernel<<<dim3(NN / 128, NN / 128, HH), 256>>>();
    out_kernel<<<PP / 64, 256>>>(onscale, onbias, Wout, bout, out);
}

// round 6
// speedup vs baseline: 1.0671x; 1.0671x over previous
#include <cuda_runtime.h>

#define NN 512
#define DD 128
#define HH 128
#define PP (NN*NN)
#define EPSV 1e-6f

// ---------------- scratch (static device allocations; no cudaMalloc) ----------------
// g_xn is reused as the einsum output buffer (strictly sequential use):
//   K1 writes g_xn -> K2 reads g_xn, writes leftT/rightT/ogT -> K3 writes g_xn (as outT)
//   -> K4 reads g_xn (as outT) + ogT.
__device__ float g_xn[(size_t)PP * DD];      // [p][d], later reused as outT [d][i*N+j]
__device__ float g_leftT[(size_t)HH * PP];   // [d][k*N+i]
__device__ float g_rightT[(size_t)HH * PP];  // [d][k*N+j]
__device__ float g_ogT[(size_t)HH * PP];     // [d][p]

__device__ __forceinline__ float sigmoidf_(float x) {
    return 1.0f / (1.0f + expf(-x));
}

// ---------------- packed f32x2 FMA (Blackwell FFMA2; ptxas never auto-fuses) -------
__device__ __forceinline__ unsigned long long pack2_(float v) {
    unsigned long long r;
    asm("mov.b64 %0, {%1, %1};" : "=l"(r) : "f"(v));
    return r;
}
__device__ __forceinline__ void ffma2_(unsigned long long& c, unsigned long long a,
                                       unsigned long long b) {
    asm("fma.rn.f32x2 %0, %1, %2, %0;" : "+l"(c) : "l"(a), "l"(b));
}

// ---------------- K1: layernorm over D=128, warp per row ----------------
__global__ void ln_kernel(const float* __restrict__ x,
                          const float* __restrict__ scale,
                          const float* __restrict__ bias) {
    int row = blockIdx.x * 8 + threadIdx.y;
    int lane = threadIdx.x;
    float4 v = reinterpret_cast<const float4*>(x + (size_t)row * DD)[lane];
    float s  = v.x + v.y + v.z + v.w;
    float sq = v.x*v.x + v.y*v.y + v.z*v.z + v.w*v.w;
    #pragma unroll
    for (int o = 16; o > 0; o >>= 1) {
        s  += __shfl_xor_sync(0xffffffffu, s, o);
        sq += __shfl_xor_sync(0xffffffffu, sq, o);
    }
    float mu = s * (1.0f / DD);
    float var = sq * (1.0f / DD) - mu * mu;
    float rstd = rsqrtf(var + EPSV);
    float4 sc = reinterpret_cast<const float4*>(scale)[lane];
    float4 bi = reinterpret_cast<const float4*>(bias)[lane];
    float4 o4;
    o4.x = (v.x - mu) * rstd * sc.x + bi.x;
    o4.y = (v.y - mu) * rstd * sc.y + bi.y;
    o4.z = (v.z - mu) * rstd * sc.z + bi.z;
    o4.w = (v.w - mu) * rstd * sc.w + bi.w;
    reinterpret_cast<float4*>(g_xn + (size_t)row * DD)[lane] = o4;
}

// ---------------- K2: fused 5-way projection + mask + gating ----------------
// Block: 64 rows (p) x 32 cols (h), all 5 weight matrices simultaneously.
// f32x2: cc=2 axis packed; weight float2 loads are natively packed u64s.
__global__ __launch_bounds__(256) void proj_kernel(
    const float* __restrict__ src_mask,
    const float* __restrict__ Wl,  const float* __restrict__ bl,
    const float* __restrict__ Wr,  const float* __restrict__ br,
    const float* __restrict__ Wlg, const float* __restrict__ blg,
    const float* __restrict__ Wrg, const float* __restrict__ brg,
    const float* __restrict__ Wog, const float* __restrict__ bog)
{
    __shared__ __align__(16) float xs[128 * 68];    // [k][r], pitch 68
    __shared__ __align__(16) float ws[5 * 16 * 34]; // [m][k][c], pitch 34; reused as stage
    int tid = threadIdx.x;
    int tx = tid & 15, ty = tid >> 4;
    int p0 = blockIdx.x * 64, h0 = blockIdx.y * 32;

    // load x tile transposed into shared: xs[k][r]
    for (int t = tid; t < 64 * 32; t += 256) {
        int r = t >> 5, k4 = t & 31;
        float4 v = *reinterpret_cast<const float4*>(g_xn + (size_t)(p0 + r) * DD + k4 * 4);
        xs[(k4*4 + 0)*68 + r] = v.x;
        xs[(k4*4 + 1)*68 + r] = v.y;
        xs[(k4*4 + 2)*68 + r] = v.z;
        xs[(k4*4 + 3)*68 + r] = v.w;
    }

    const float* Wm[5] = {Wl, Wr, Wlg, Wrg, Wog};
    unsigned long long acc2[5][4] = {};  // [m][rr], each packs (cc0, cc1)

    int lc = tid & 31, lk = tid >> 5;  // lk: 0..7
    for (int kk = 0; kk < 128; kk += 16) {
        __syncthreads();
        #pragma unroll
        for (int m = 0; m < 5; m++) {
            ws[(m*16 + lk    )*34 + lc] = Wm[m][(kk + lk    ) * HH + h0 + lc];
            ws[(m*16 + lk + 8)*34 + lc] = Wm[m][(kk + lk + 8) * HH + h0 + lc];
        }
        __syncthreads();
        #pragma unroll
        for (int k = 0; k < 16; k++) {
            float4 a = *reinterpret_cast<const float4*>(&xs[(kk + k)*68 + tx*4]);
            unsigned long long ap[4] = {pack2_(a.x), pack2_(a.y), pack2_(a.z), pack2_(a.w)};
            #pragma unroll
            for (int m = 0; m < 5; m++) {
                unsigned long long w =
                    *reinterpret_cast<const unsigned long long*>(&ws[(m*16 + k)*34 + ty*2]);
                #pragma unroll
                for (int rr = 0; rr < 4; rr++)
                    ffma2_(acc2[m][rr], ap[rr], w);
            }
        }
    }

    // unpack accumulators
    float acc[5][4][2];
    #pragma unroll
    for (int m = 0; m < 5; m++)
        #pragma unroll
        for (int rr = 0; rr < 4; rr++) {
            float2 v = *reinterpret_cast<float2*>(&acc2[m][rr]);
            acc[m][rr][0] = v.x; acc[m][rr][1] = v.y;
        }

    // epilogue: bias + mask + sigmoid gating
    float mval[4];
    #pragma unroll
    for (int rr = 0; rr < 4; rr++) {
        int p = p0 + tx*4 + rr;
        mval[rr] = src_mask[p >> 9] * src_mask[p & (NN - 1)];
    }
    float Lv[4][2], Rv[4][2], Gv[4][2];
    #pragma unroll
    for (int cc = 0; cc < 2; cc++) {
        int h = h0 + ty*2 + cc;
        float bL = bl[h], bR = br[h], bLG = blg[h], bRG = brg[h], bOG = bog[h];
        #pragma unroll
        for (int rr = 0; rr < 4; rr++) {
            Lv[rr][cc] = (acc[0][rr][cc] + bL) * mval[rr] * sigmoidf_(acc[2][rr][cc] + bLG);
            Rv[rr][cc] = (acc[1][rr][cc] + bR) * mval[rr] * sigmoidf_(acc[3][rr][cc] + bRG);
            Gv[rr][cc] = sigmoidf_(acc[4][rr][cc] + bOG);
        }
    }

    // staged transposed writes (d-major), coalesced. stage[c][r], pitch 68; fits in ws.
    float* stage = ws;
    float* dsts[3] = {g_leftT, g_rightT, g_ogT};
    for (int which = 0; which < 3; which++) {
        __syncthreads();
        #pragma unroll
        for (int cc = 0; cc < 2; cc++)
            #pragma unroll
            for (int rr = 0; rr < 4; rr++) {
                float v = (which == 0) ? Lv[rr][cc] : (which == 1) ? Rv[rr][cc] : Gv[rr][cc];
                stage[(ty*2 + cc)*68 + tx*4 + rr] = v;
            }
        __syncthreads();
        float* dst = dsts[which];
        for (int t = tid; t < 32 * 64; t += 256) {
            int c = t >> 6, r = t & 63;
            dst[(size_t)(h0 + c) * PP + p0 + r] = stage[c*68 + r];
        }
    }
}

// ---------------- K3: triangle einsum = 128 batched SGEMMs (K-major A and B) ----------------
// out[d][i][j] = sum_k leftT[d][k][i] * rightT[d][k][j]
// 128x128 tile, 8x8 per thread as 8x4 f32x2 accumulators; B pairs natively packed.
__global__ __launch_bounds__(256) void einsum_kernel() {
    __shared__ __align__(16) float As[16 * 132];
    __shared__ __align__(16) float Bs[16 * 132];
    int tid = threadIdx.x;
    int tx = tid & 15, ty = tid >> 4;
    int j0 = blockIdx.x * 128, i0 = blockIdx.y * 128, d = blockIdx.z;
    const float* L = g_leftT  + (size_t)d * PP;
    const float* R = g_rightT + (size_t)d * PP;
    unsigned long long acc2[8][4] = {};  // [rr][cp], each packs (cc, cc+1)
    int li = tid & 31, lk = tid >> 5;  // li: float4 col 0..31, lk: row 0..7
    for (int kk = 0; kk < NN; kk += 16) {
        __syncthreads();
        #pragma unroll
        for (int q = 0; q < 2; q++) {
            *reinterpret_cast<float4*>(&As[(lk + q*8)*132 + li*4]) =
                *reinterpret_cast<const float4*>(&L[(size_t)(kk + lk + q*8) * NN + i0 + li*4]);
            *reinterpret_cast<float4*>(&Bs[(lk + q*8)*132 + li*4]) =
                *reinterpret_cast<const float4*>(&R[(size_t)(kk + lk + q*8) * NN + j0 + li*4]);
        }
        __syncthreads();
        #pragma unroll
        for (int k = 0; k < 16; k++) {
            float a[8];
            *reinterpret_cast<float4*>(&a[0]) = *reinterpret_cast<const float4*>(&As[k*132 + ty*8]);
            *reinterpret_cast<float4*>(&a[4]) = *reinterpret_cast<const float4*>(&As[k*132 + ty*8 + 4]);
            ulonglong2 b01 = *reinterpret_cast<const ulonglong2*>(&Bs[k*132 + tx*8]);
            ulonglong2 b23 = *reinterpret_cast<const ulonglong2*>(&Bs[k*132 + tx*8 + 4]);
            unsigned long long bp[4] = {b01.x, b01.y, b23.x, b23.y};
            #pragma unroll
            for (int rr = 0; rr < 8; rr++) {
                unsigned long long ap = pack2_(a[rr]);
                #pragma unroll
                for (int cp = 0; cp < 4; cp++)
                    ffma2_(acc2[rr][cp], ap, bp[cp]);
            }
        }
    }
    float* O = g_xn + (size_t)d * PP;   // reuse g_xn as outT
    #pragma unroll
    for (int rr = 0; rr < 8; rr++) {
        size_t base = (size_t)(i0 + ty*8 + rr) * NN + j0 + tx*8;
        // acc2[rr] reinterpreted as 8 consecutive floats = columns cc..cc+7 in order
        const float* af = reinterpret_cast<const float*>(acc2[rr]);
        *reinterpret_cast<float4*>(&O[base])     = make_float4(af[0], af[1], af[2], af[3]);
        *reinterpret_cast<float4*>(&O[base + 4]) = make_float4(af[4], af[5], af[6], af[7]);
    }
}

// ---------------- K4: out-layernorm * ogate, then @ W_out + b_out ----------------
// Block: 64 rows (p). Transpose outT slab into shared, LN over d, gate, then GEMM.
__global__ __launch_bounds__(256) void out_kernel(
    const float* __restrict__ onscale, const float* __restrict__ onbias,
    const float* __restrict__ Wout,    const float* __restrict__ bout,
    float* __restrict__ out)
{
    __shared__ __align__(16) float sh[128 * 68];   // [d][r]
    __shared__ __align__(16) float wsh[16 * 132];  // [k][c]
    __shared__ float red_s[4][64];
    __shared__ float red_q[4][64];
    int tid = threadIdx.x;
    int p0 = blockIdx.x * 64;
    const float* outT = g_xn;   // einsum result lives in g_xn

    for (int t = tid; t < 128 * 64; t += 256) {
        int dd = t >> 6, r = t & 63;
        sh[dd*68 + r] = outT[(size_t)dd * PP + p0 + r];
    }
    __syncthreads();

    int r = tid & 63, q = tid >> 6;
    float s = 0.f, sq = 0.f;
    #pragma unroll
    for (int u = 0; u < 32; u++) {
        float v = sh[(q*32 + u)*68 + r];
        s += v; sq += v*v;
    }
    red_s[q][r] = s; red_q[q][r] = sq;
    __syncthreads();
    float st  = red_s[0][r] + red_s[1][r] + red_s[2][r] + red_s[3][r];
    float sqt = red_q[0][r] + red_q[1][r] + red_q[2][r] + red_q[3][r];
    float mu = st * (1.0f / HH);
    float rstd = rsqrtf(sqt * (1.0f / HH) - mu*mu + EPSV);
    #pragma unroll
    for (int u = 0; u < 32; u++) {
        int dd = q*32 + u;
        float v = sh[dd*68 + r];
        float g = g_ogT[(size_t)dd * PP + p0 + r];
        sh[dd*68 + r] = ((v - mu) * rstd * onscale[dd] + onbias[dd]) * g;
    }

    // GEMM: out[p][c] = sum_d sh[d][p] * Wout[d][c] + bout[c]
    int tx = tid & 15, ty = tid >> 4;   // rows tx*4.., cols ty*8..
    unsigned long long acc2[4][4] = {};  // [rr][cp], packs (cc, cc+1)
    int lc = tid & 127, lk2 = tid >> 7;  // lk2: 0..1
    for (int kk = 0; kk < 128; kk += 16) {
        __syncthreads();
        #pragma unroll
        for (int qq = 0; qq < 8; qq++)
            wsh[(lk2 + qq*2)*132 + lc] = Wout[(size_t)(kk + lk2 + qq*2) * DD + lc];
        __syncthreads();
        #pragma unroll
        for (int k = 0; k < 16; k++) {
            float4 a = *reinterpret_cast<const float4*>(&sh[(kk + k)*68 + tx*4]);
            unsigned long long ap[4] = {pack2_(a.x), pack2_(a.y), pack2_(a.z), pack2_(a.w)};
            ulonglong2 w01 = *reinterpret_cast<const ulonglong2*>(&wsh[k*132 + ty*8]);
            ulonglong2 w23 = *reinterpret_cast<const ulonglong2*>(&wsh[k*132 + ty*8 + 4]);
            unsigned long long wp[4] = {w01.x, w01.y, w23.x, w23.y};
            #pragma unroll
            for (int rr = 0; rr < 4; rr++)
                #pragma unroll
                for (int cp = 0; cp < 4; cp++)
                    ffma2_(acc2[rr][cp], ap[rr], wp[cp]);
        }
    }
    float bb[8];
    *reinterpret_cast<float4*>(&bb[0]) = *reinterpret_cast<const float4*>(&bout[ty*8]);
    *reinterpret_cast<float4*>(&bb[4]) = *reinterpret_cast<const float4*>(&bout[ty*8 + 4]);
    #pragma unroll
    for (int rr = 0; rr < 4; rr++) {
        size_t base = (size_t)(p0 + tx*4 + rr) * DD + ty*8;
        const float* af = reinterpret_cast<const float*>(acc2[rr]);
        *reinterpret_cast<float4*>(&out[base]) =
            make_float4(af[0] + bb[0], af[1] + bb[1], af[2] + bb[2], af[3] + bb[3]);
        *reinterpret_cast<float4*>(&out[base + 4]) =
            make_float4(af[4] + bb[4], af[5] + bb[5], af[6] + bb[6], af[7] + bb[7]);
    }
}

// ---------------- launch ----------------
extern "C" void kernel_launch(void* const* d_in, const int* in_sizes, int n_in,
                              void* d_out, int out_size) {
    const float* x        = (const float*)d_in[0];
    const float* src_mask = (const float*)d_in[1];
    const float* nscale   = (const float*)d_in[2];
    const float* nbias    = (const float*)d_in[3];
    const float* Wl       = (const float*)d_in[4];
    const float* bl       = (const float*)d_in[5];
    const float* Wr       = (const float*)d_in[6];
    const float* br       = (const float*)d_in[7];
    const float* Wlg      = (const float*)d_in[8];
    const float* blg      = (const float*)d_in[9];
    const float* Wrg      = (const float*)d_in[10];
    const float* brg      = (const float*)d_in[11];
    const float* Wog      = (const float*)d_in[12];
    const float* bog      = (const float*)d_in[13];
    const float* onscale  = (const float*)d_in[14];
    const float* onbias   = (const float*)d_in[15];
    const float* Wout     = (const float*)d_in[16];
    const float* bout     = (const float*)d_in[17];
    float* out = (float*)d_out;

    ln_kernel<<<PP / 8, dim3(32, 8)>>>(x, nscale, nbias);
    proj_kernel<<<dim3(PP / 64, HH / 32), 256>>>(src_mask, Wl, bl, Wr, br,
                                                 Wlg, blg, Wrg, brg, Wog, bog);
    einsum_kernel<<<dim3(NN / 128, NN / 128, HH), 256>>>();
    out_kernel<<<PP / 64, 256>>>(onscale, onbias, Wout, bout, out);
}

// round 11
// speedup vs baseline: 1.1282x; 1.0572x over previous
#include <cuda_runtime.h>
#include <cuda_bf16.h>
#include <cstdint>

#define NN 512
#define DD 128
#define HH 128
#define PP (NN*NN)
#define EPSV 1e-6f

// ---------------- scratch (static device allocations; no cudaMalloc) ----------------
// Sequence: K1 writes g_xn -> K2(proj) reads g_xn, writes leftT/rightT/ogT ->
// K2b(split) reads leftT/rightT, writes bf16 hi/lo planes -> K3(einsum_mma) writes g_xn
// (as outT) -> K4 reads g_xn + ogT.
__device__ float g_xn[(size_t)PP * DD];      // [p][d], later reused as outT [d][i*N+j]
__device__ float g_leftT[(size_t)HH * PP];   // [d][k*N+i]  (f32, proj output)
__device__ float g_rightT[(size_t)HH * PP];  // [d][k*N+j]
__device__ float g_ogT[(size_t)HH * PP];     // [d][p]
// bf16 split planes in K-major layout [d][i][k] / [d][j][k]
__device__ __nv_bfloat16 g_AH[(size_t)HH * PP];
__device__ __nv_bfloat16 g_AL[(size_t)HH * PP];
__device__ __nv_bfloat16 g_BH[(size_t)HH * PP];
__device__ __nv_bfloat16 g_BL[(size_t)HH * PP];

__device__ __forceinline__ float sigmoidf_(float x) {
    return 1.0f / (1.0f + expf(-x));
}

// ---------------- packed f32x2 FMA ----------------
__device__ __forceinline__ unsigned long long pack2_(float v) {
    unsigned long long r;
    asm("mov.b64 %0, {%1, %1};" : "=l"(r) : "f"(v));
    return r;
}
__device__ __forceinline__ void ffma2_(unsigned long long& c, unsigned long long a,
                                       unsigned long long b) {
    asm("fma.rn.f32x2 %0, %1, %2, %0;" : "+l"(c) : "l"(a), "l"(b));
}

// ---------------- warp-MMA helpers (base ISA: sm_80+, compiles on sm_103) -------------
__device__ __forceinline__ uint32_t smem_u32_(const void* p) {
    uint32_t a;
    asm("{ .reg .u64 t; cvta.to.shared.u64 t, %1; cvt.u32.u64 %0, t; }" : "=r"(a) : "l"(p));
    return a;
}
__device__ __forceinline__ void ldmx4_(uint32_t& r0, uint32_t& r1, uint32_t& r2,
                                       uint32_t& r3, uint32_t addr) {
    asm volatile("ldmatrix.sync.aligned.m8n8.x4.shared.b16 {%0,%1,%2,%3}, [%4];"
                 : "=r"(r0), "=r"(r1), "=r"(r2), "=r"(r3) : "r"(addr));
}
__device__ __forceinline__ void mma16816_(float* c, const uint32_t* a, uint32_t b0,
                                          uint32_t b1) {
    asm volatile(
        "mma.sync.aligned.m16n8k16.row.col.f32.bf16.bf16.f32 "
        "{%0,%1,%2,%3}, {%4,%5,%6,%7}, {%8,%9}, {%0,%1,%2,%3};"
        : "+f"(c[0]), "+f"(c[1]), "+f"(c[2]), "+f"(c[3])
        : "r"(a[0]), "r"(a[1]), "r"(a[2]), "r"(a[3]), "r"(b0), "r"(b1));
}

// ---------------- K1: layernorm over D=128, warp per row ----------------
__global__ void ln_kernel(const float* __restrict__ x,
                          const float* __restrict__ scale,
                          const float* __restrict__ bias) {
    int row = blockIdx.x * 8 + threadIdx.y;
    int lane = threadIdx.x;
    float4 v = reinterpret_cast<const float4*>(x + (size_t)row * DD)[lane];
    float s  = v.x + v.y + v.z + v.w;
    float sq = v.x*v.x + v.y*v.y + v.z*v.z + v.w*v.w;
    #pragma unroll
    for (int o = 16; o > 0; o >>= 1) {
        s  += __shfl_xor_sync(0xffffffffu, s, o);
        sq += __shfl_xor_sync(0xffffffffu, sq, o);
    }
    float mu = s * (1.0f / DD);
    float var = sq * (1.0f / DD) - mu * mu;
    float rstd = rsqrtf(var + EPSV);
    float4 sc = reinterpret_cast<const float4*>(scale)[lane];
    float4 bi = reinterpret_cast<const float4*>(bias)[lane];
    float4 o4;
    o4.x = (v.x - mu) * rstd * sc.x + bi.x;
    o4.y = (v.y - mu) * rstd * sc.y + bi.y;
    o4.z = (v.z - mu) * rstd * sc.z + bi.z;
    o4.w = (v.w - mu) * rstd * sc.w + bi.w;
    reinterpret_cast<float4*>(g_xn + (size_t)row * DD)[lane] = o4;
}

// ---------------- K2: fused 5-way projection + mask + gating (unchanged, passing) ------
__global__ __launch_bounds__(256) void proj_kernel(
    const float* __restrict__ src_mask,
    const float* __restrict__ Wl,  const float* __restrict__ bl,
    const float* __restrict__ Wr,  const float* __restrict__ br,
    const float* __restrict__ Wlg, const float* __restrict__ blg,
    const float* __restrict__ Wrg, const float* __restrict__ brg,
    const float* __restrict__ Wog, const float* __restrict__ bog)
{
    __shared__ __align__(16) float xs[128 * 68];
    __shared__ __align__(16) float ws[5 * 16 * 34];
    int tid = threadIdx.x;
    int tx = tid & 15, ty = tid >> 4;
    int p0 = blockIdx.x * 64, h0 = blockIdx.y * 32;

    for (int t = tid; t < 64 * 32; t += 256) {
        int r = t >> 5, k4 = t & 31;
        float4 v = *reinterpret_cast<const float4*>(g_xn + (size_t)(p0 + r) * DD + k4 * 4);
        xs[(k4*4 + 0)*68 + r] = v.x;
        xs[(k4*4 + 1)*68 + r] = v.y;
        xs[(k4*4 + 2)*68 + r] = v.z;
        xs[(k4*4 + 3)*68 + r] = v.w;
    }

    const float* Wm[5] = {Wl, Wr, Wlg, Wrg, Wog};
    unsigned long long acc2[5][4] = {};

    int lc = tid & 31, lk = tid >> 5;
    for (int kk = 0; kk < 128; kk += 16) {
        __syncthreads();
        #pragma unroll
        for (int m = 0; m < 5; m++) {
            ws[(m*16 + lk    )*34 + lc] = Wm[m][(kk + lk    ) * HH + h0 + lc];
            ws[(m*16 + lk + 8)*34 + lc] = Wm[m][(kk + lk + 8) * HH + h0 + lc];
        }
        __syncthreads();
        #pragma unroll
        for (int k = 0; k < 16; k++) {
            float4 a = *reinterpret_cast<const float4*>(&xs[(kk + k)*68 + tx*4]);
            unsigned long long ap[4] = {pack2_(a.x), pack2_(a.y), pack2_(a.z), pack2_(a.w)};
            #pragma unroll
            for (int m = 0; m < 5; m++) {
                unsigned long long w =
                    *reinterpret_cast<const unsigned long long*>(&ws[(m*16 + k)*34 + ty*2]);
                #pragma unroll
                for (int rr = 0; rr < 4; rr++)
                    ffma2_(acc2[m][rr], ap[rr], w);
            }
        }
    }

    float acc[5][4][2];
    #pragma unroll
    for (int m = 0; m < 5; m++)
        #pragma unroll
        for (int rr = 0; rr < 4; rr++) {
            float2 v = *reinterpret_cast<float2*>(&acc2[m][rr]);
            acc[m][rr][0] = v.x; acc[m][rr][1] = v.y;
        }

    float mval[4];
    #pragma unroll
    for (int rr = 0; rr < 4; rr++) {
        int p = p0 + tx*4 + rr;
        mval[rr] = src_mask[p >> 9] * src_mask[p & (NN - 1)];
    }
    float Lv[4][2], Rv[4][2], Gv[4][2];
    #pragma unroll
    for (int cc = 0; cc < 2; cc++) {
        int h = h0 + ty*2 + cc;
        float bL = bl[h], bR = br[h], bLG = blg[h], bRG = brg[h], bOG = bog[h];
        #pragma unroll
        for (int rr = 0; rr < 4; rr++) {
            Lv[rr][cc] = (acc[0][rr][cc] + bL) * mval[rr] * sigmoidf_(acc[2][rr][cc] + bLG);
            Rv[rr][cc] = (acc[1][rr][cc] + bR) * mval[rr] * sigmoidf_(acc[3][rr][cc] + bRG);
            Gv[rr][cc] = sigmoidf_(acc[4][rr][cc] + bOG);
        }
    }

    float* stage = ws;
    float* dsts[3] = {g_leftT, g_rightT, g_ogT};
    for (int which = 0; which < 3; which++) {
        __syncthreads();
        #pragma unroll
        for (int cc = 0; cc < 2; cc++)
            #pragma unroll
            for (int rr = 0; rr < 4; rr++) {
                float v = (which == 0) ? Lv[rr][cc] : (which == 1) ? Rv[rr][cc] : Gv[rr][cc];
                stage[(ty*2 + cc)*68 + tx*4 + rr] = v;
            }
        __syncthreads();
        float* dst = dsts[which];
        for (int t = tid; t < 32 * 64; t += 256) {
            int c = t >> 6, r = t & 63;
            dst[(size_t)(h0 + c) * PP + p0 + r] = stage[c*68 + r];
        }
    }
}

// ---------------- K2b: transpose + bf16 hi/lo split ----------------
// [d][k][i] f32 -> [d][i][k] bf16 hi & lo, for both left and right. 64x64 tiles.
__global__ __launch_bounds__(256) void split_kernel() {
    __shared__ float tl[64][65];
    __shared__ float tr[64][65];
    int d = blockIdx.z;
    int i0 = blockIdx.x * 64, k0 = blockIdx.y * 64;
    const float* L  = g_leftT  + (size_t)d * PP;
    const float* Rm = g_rightT + (size_t)d * PP;
    int t = threadIdx.x, kr = t >> 2, sg = t & 3;
    #pragma unroll
    for (int q = 0; q < 4; q++) {
        int c = sg * 16 + q * 4;
        float4 v = *reinterpret_cast<const float4*>(&L[(size_t)(k0 + kr) * NN + i0 + c]);
        tl[kr][c] = v.x; tl[kr][c+1] = v.y; tl[kr][c+2] = v.z; tl[kr][c+3] = v.w;
        float4 w = *reinterpret_cast<const float4*>(&Rm[(size_t)(k0 + kr) * NN + i0 + c]);
        tr[kr][c] = w.x; tr[kr][c+1] = w.y; tr[kr][c+2] = w.z; tr[kr][c+3] = w.w;
    }
    __syncthreads();
    int ii = kr;
    #pragma unroll
    for (int q = 0; q < 4; q++) {
        int kk = sg * 16 + q * 4;
        size_t base = (size_t)d * PP + (size_t)(i0 + ii) * NN + k0 + kk;
        float lv[4], rv[4];
        #pragma unroll
        for (int u = 0; u < 4; u++) { lv[u] = tl[kk + u][ii]; rv[u] = tr[kk + u][ii]; }
        uint2 lh, ll, rh, rl;
        {
            unsigned h[4], l[4];
            #pragma unroll
            for (int u = 0; u < 4; u++) {
                __nv_bfloat16 hb = __float2bfloat16_rn(lv[u]);
                __nv_bfloat16 lb = __float2bfloat16_rn(lv[u] - __bfloat162float(hb));
                h[u] = __bfloat16_as_ushort(hb); l[u] = __bfloat16_as_ushort(lb);
            }
            lh = make_uint2(h[0] | (h[1] << 16), h[2] | (h[3] << 16));
            ll = make_uint2(l[0] | (l[1] << 16), l[2] | (l[3] << 16));
            #pragma unroll
            for (int u = 0; u < 4; u++) {
                __nv_bfloat16 hb = __float2bfloat16_rn(rv[u]);
                __nv_bfloat16 lb = __float2bfloat16_rn(rv[u] - __bfloat162float(hb));
                h[u] = __bfloat16_as_ushort(hb); l[u] = __bfloat16_as_ushort(lb);
            }
            rh = make_uint2(h[0] | (h[1] << 16), h[2] | (h[3] << 16));
            rl = make_uint2(l[0] | (l[1] << 16), l[2] | (l[3] << 16));
        }
        *reinterpret_cast<uint2*>(&g_AH[base]) = lh;
        *reinterpret_cast<uint2*>(&g_AL[base]) = ll;
        *reinterpret_cast<uint2*>(&g_BH[base]) = rh;
        *reinterpret_cast<uint2*>(&g_BL[base]) = rl;
    }
}

// ---------------- K3: triangle einsum via mma.sync bf16 hi/lo (base-ISA tensor cores) --
// out[d][i][j] = sum_k L[d][i][k] * R[d][j][k]
// CTA 128(i)x128(j), K=512 in KC=32 stages. 8 warps in 4x2; warp tile 32x64.
// 3 passes: AhBh + AhBl + AlBh into fp32 acc (~1e-5 effective error).
#define EPITCH 40   // bf16 elems per smem row (32 data + 8 pad); 80B row stride
__global__ __launch_bounds__(256) void einsum_mma() {
    __shared__ __align__(16) __nv_bfloat16 sAH[128 * EPITCH];
    __shared__ __align__(16) __nv_bfloat16 sAL[128 * EPITCH];
    __shared__ __align__(16) __nv_bfloat16 sBH[128 * EPITCH];
    __shared__ __align__(16) __nv_bfloat16 sBL[128 * EPITCH];
    int tid = threadIdx.x, wid = tid >> 5, lane = tid & 31;
    int wm = wid & 3, wn = wid >> 2;            // warp tile: i += wm*32, j += wn*64
    int j0 = blockIdx.x * 128, i0 = blockIdx.y * 128, d = blockIdx.z;

    const __nv_bfloat16* pAH = g_AH + (size_t)d * PP;
    const __nv_bfloat16* pAL = g_AL + (size_t)d * PP;
    const __nv_bfloat16* pBH = g_BH + (size_t)d * PP;
    const __nv_bfloat16* pBL = g_BL + (size_t)d * PP;

    uint32_t bAH = smem_u32_(sAH), bAL = smem_u32_(sAL);
    uint32_t bBH = smem_u32_(sBH), bBL = smem_u32_(sBL);

    float acc[2][8][4] = {};   // [mt][nt][4]

    for (int kk = 0; kk < NN; kk += 32) {
        __syncthreads();
        // load 4 planes: 128 rows x 32 bf16 each; 512 16B-segments per plane
        #pragma unroll
        for (int it = 0; it < 2; it++) {
            int idx = tid + it * 256;
            int r = idx >> 2, sg = idx & 3;
            uint32_t so = (uint32_t)(r * EPITCH + sg * 8) * 2;
            size_t ga = (size_t)(i0 + r) * NN + kk + sg * 8;
            size_t gb = (size_t)(j0 + r) * NN + kk + sg * 8;
            *reinterpret_cast<uint4*>((char*)sAH + so) = *reinterpret_cast<const uint4*>(pAH + ga);
            *reinterpret_cast<uint4*>((char*)sAL + so) = *reinterpret_cast<const uint4*>(pAL + ga);
            *reinterpret_cast<uint4*>((char*)sBH + so) = *reinterpret_cast<const uint4*>(pBH + gb);
            *reinterpret_cast<uint4*>((char*)sBL + so) = *reinterpret_cast<const uint4*>(pBL + gb);
        }
        __syncthreads();

        #pragma unroll
        for (int ks = 0; ks < 2; ks++) {
            int k0 = ks * 16;
            // A fragments (hi & lo), 2 m16 tiles each
            uint32_t aH[2][4], aL[2][4];
            #pragma unroll
            for (int mt = 0; mt < 2; mt++) {
                int row = wm * 32 + mt * 16 + (lane & 15);
                int col = k0 + (lane >> 4) * 8;
                uint32_t off = (uint32_t)(row * EPITCH + col) * 2;
                ldmx4_(aH[mt][0], aH[mt][1], aH[mt][2], aH[mt][3], bAH + off);
                ldmx4_(aL[mt][0], aL[mt][1], aL[mt][2], aL[mt][3], bAL + off);
            }
            // B fragments (hi & lo), 8 n8 tiles loaded as 4 x4-pairs
            uint32_t bH[8][2], bL[8][2];
            #pragma unroll
            for (int np = 0; np < 4; np++) {
                int grp = lane >> 3, r8 = lane & 7;
                int nrow = wn * 64 + np * 16 + (grp >> 1) * 8 + r8;
                int col = k0 + (grp & 1) * 8;
                uint32_t off = (uint32_t)(nrow * EPITCH + col) * 2;
                uint32_t r0, r1, r2, r3;
                ldmx4_(r0, r1, r2, r3, bBH + off);
                bH[np*2][0] = r0; bH[np*2][1] = r1; bH[np*2+1][0] = r2; bH[np*2+1][1] = r3;
                ldmx4_(r0, r1, r2, r3, bBL + off);
                bL[np*2][0] = r0; bL[np*2][1] = r1; bL[np*2+1][0] = r2; bL[np*2+1][1] = r3;
            }
            #pragma unroll
            for (int mt = 0; mt < 2; mt++)
                #pragma unroll
                for (int nt = 0; nt < 8; nt++) {
                    mma16816_(acc[mt][nt], aH[mt], bH[nt][0], bH[nt][1]);
                    mma16816_(acc[mt][nt], aH[mt], bL[nt][0], bL[nt][1]);
                    mma16816_(acc[mt][nt], aL[mt], bH[nt][0], bH[nt][1]);
                }
        }
    }

    // epilogue: c0,c1 -> (row, j..j+1); c2,c3 -> (row+8, j..j+1)
    float* O = g_xn + (size_t)d * PP;
    #pragma unroll
    for (int mt = 0; mt < 2; mt++) {
        int ib = i0 + wm * 32 + mt * 16 + (lane >> 2);
        #pragma unroll
        for (int nt = 0; nt < 8; nt++) {
            int jb = j0 + wn * 64 + nt * 8 + (lane & 3) * 2;
            *reinterpret_cast<float2*>(&O[(size_t)ib * NN + jb]) =
                make_float2(acc[mt][nt][0], acc[mt][nt][1]);
            *reinterpret_cast<float2*>(&O[(size_t)(ib + 8) * NN + jb]) =
                make_float2(acc[mt][nt][2], acc[mt][nt][3]);
        }
    }
}

// ---------------- K4: out-layernorm * ogate, then @ W_out + b_out (unchanged) ----------
__global__ __launch_bounds__(256) void out_kernel(
    const float* __restrict__ onscale, const float* __restrict__ onbias,
    const float* __restrict__ Wout,    const float* __restrict__ bout,
    float* __restrict__ out)
{
    __shared__ __align__(16) float sh[128 * 68];
    __shared__ __align__(16) float wsh[16 * 132];
    __shared__ float red_s[4][64];
    __shared__ float red_q[4][64];
    int tid = threadIdx.x;
    int p0 = blockIdx.x * 64;
    const float* outT = g_xn;

    for (int t = tid; t < 128 * 64; t += 256) {
        int dd = t >> 6, r = t & 63;
        sh[dd*68 + r] = outT[(size_t)dd * PP + p0 + r];
    }
    __syncthreads();

    int r = tid & 63, q = tid >> 6;
    float s = 0.f, sq = 0.f;
    #pragma unroll
    for (int u = 0; u < 32; u++) {
        float v = sh[(q*32 + u)*68 + r];
        s += v; sq += v*v;
    }
    red_s[q][r] = s; red_q[q][r] = sq;
    __syncthreads();
    float st  = red_s[0][r] + red_s[1][r] + red_s[2][r] + red_s[3][r];
    float sqt = red_q[0][r] + red_q[1][r] + red_q[2][r] + red_q[3][r];
    float mu = st * (1.0f / HH);
    float rstd = rsqrtf(sqt * (1.0f / HH) - mu*mu + EPSV);
    #pragma unroll
    for (int u = 0; u < 32; u++) {
        int dd = q*32 + u;
        float v = sh[dd*68 + r];
        float g = g_ogT[(size_t)dd * PP + p0 + r];
        sh[dd*68 + r] = ((v - mu) * rstd * onscale[dd] + onbias[dd]) * g;
    }

    int tx = tid & 15, ty = tid >> 4;
    unsigned long long acc2[4][4] = {};
    int lc = tid & 127, lk2 = tid >> 7;
    for (int kk = 0; kk < 128; kk += 16) {
        __syncthreads();
        #pragma unroll
        for (int qq = 0; qq < 8; qq++)
            wsh[(lk2 + qq*2)*132 + lc] = Wout[(size_t)(kk + lk2 + qq*2) * DD + lc];
        __syncthreads();
        #pragma unroll
        for (int k = 0; k < 16; k++) {
            float4 a = *reinterpret_cast<const float4*>(&sh[(kk + k)*68 + tx*4]);
            unsigned long long ap[4] = {pack2_(a.x), pack2_(a.y), pack2_(a.z), pack2_(a.w)};
            ulonglong2 w01 = *reinterpret_cast<const ulonglong2*>(&wsh[k*132 + ty*8]);
            ulonglong2 w23 = *reinterpret_cast<const ulonglong2*>(&wsh[k*132 + ty*8 + 4]);
            unsigned long long wp[4] = {w01.x, w01.y, w23.x, w23.y};
            #pragma unroll
            for (int rr = 0; rr < 4; rr++)
                #pragma unroll
                for (int cp = 0; cp < 4; cp++)
                    ffma2_(acc2[rr][cp], ap[rr], wp[cp]);
        }
    }
    float bb[8];
    *reinterpret_cast<float4*>(&bb[0]) = *reinterpret_cast<const float4*>(&bout[ty*8]);
    *reinterpret_cast<float4*>(&bb[4]) = *reinterpret_cast<const float4*>(&bout[ty*8 + 4]);
    #pragma unroll
    for (int rr = 0; rr < 4; rr++) {
        size_t base = (size_t)(p0 + tx*4 + rr) * DD + ty*8;
        const float* af = reinterpret_cast<const float*>(acc2[rr]);
        *reinterpret_cast<float4*>(&out[base]) =
            make_float4(af[0] + bb[0], af[1] + bb[1], af[2] + bb[2], af[3] + bb[3]);
        *reinterpret_cast<float4*>(&out[base + 4]) =
            make_float4(af[4] + bb[4], af[5] + bb[5], af[6] + bb[6], af[7] + bb[7]);
    }
}

// ---------------- launch ----------------
extern "C" void kernel_launch(void* const* d_in, const int* in_sizes, int n_in,
                              void* d_out, int out_size) {
    const float* x        = (const float*)d_in[0];
    const float* src_mask = (const float*)d_in[1];
    const float* nscale   = (const float*)d_in[2];
    const float* nbias    = (const float*)d_in[3];
    const float* Wl       = (const float*)d_in[4];
    const float* bl       = (const float*)d_in[5];
    const float* Wr       = (const float*)d_in[6];
    const float* br       = (const float*)d_in[7];
    const float* Wlg      = (const float*)d_in[8];
    const float* blg      = (const float*)d_in[9];
    const float* Wrg      = (const float*)d_in[10];
    const float* brg      = (const float*)d_in[11];
    const float* Wog      = (const float*)d_in[12];
    const float* bog      = (const float*)d_in[13];
    const float* onscale  = (const float*)d_in[14];
    const float* onbias   = (const float*)d_in[15];
    const float* Wout     = (const float*)d_in[16];
    const float* bout     = (const float*)d_in[17];
    float* out = (float*)d_out;

    ln_kernel<<<PP / 8, dim3(32, 8)>>>(x, nscale, nbias);
    proj_kernel<<<dim3(PP / 64, HH / 32), 256>>>(src_mask, Wl, bl, Wr, br,
                                                 Wlg, blg, Wrg, brg, Wog, bog);
    split_kernel<<<dim3(NN / 64, NN / 64, HH), 256>>>();
    einsum_mma<<<dim3(NN / 128, NN / 128, HH), 256>>>();
    out_kernel<<<PP / 64, 256>>>(onscale, onbias, Wout, bout, out);
}

// round 14
// speedup vs baseline: 1.5298x; 1.3559x over previous
#include <cuda_runtime.h>
#include <cuda_bf16.h>
#include <cstdint>

#define NN 512
#define DD 128
#define HH 128
#define PP (NN*NN)
#define EPSV 1e-6f

// ---------------- scratch (static device allocations; no cudaMalloc) ----------------
// Sequence: K1(ln) writes XH/XL (aliased in g_xn) -> split_w writes g_WH/g_WL ->
// K2(proj_mma) reads XH/XL + W planes, writes leftT/rightT/ogT (f32, d-major) ->
// K2b(split) reads leftT/rightT, writes bf16 hi/lo planes -> K3(einsum_mma) writes g_xn
// (as f32 outT; overwrites XH/XL which are dead by then) -> K4 reads g_xn + ogT.
__device__ float g_xn[(size_t)PP * DD];      // ln: bf16 XH|XL planes; einsum: f32 outT
__device__ float g_leftT[(size_t)HH * PP];   // [d][k*N+i]  (f32, proj output)
__device__ float g_rightT[(size_t)HH * PP];  // [d][k*N+j]
__device__ float g_ogT[(size_t)HH * PP];     // [d][p]
// bf16 split planes in K-major layout [d][i][k] / [d][j][k]
__device__ __nv_bfloat16 g_AH[(size_t)HH * PP];
__device__ __nv_bfloat16 g_AL[(size_t)HH * PP];
__device__ __nv_bfloat16 g_BH[(size_t)HH * PP];
__device__ __nv_bfloat16 g_BL[(size_t)HH * PP];
// weight planes, K-major transposed: [m][h][k], m: 0=Wl 1=Wr 2=Wlg 3=Wrg 4=Wog
__device__ __nv_bfloat16 g_WH[5 * DD * HH];
__device__ __nv_bfloat16 g_WL[5 * DD * HH];

__device__ __forceinline__ float sigmoidf_(float x) {
    return 1.0f / (1.0f + expf(-x));
}

// ---------------- packed f32x2 FMA ----------------
__device__ __forceinline__ unsigned long long pack2_(float v) {
    unsigned long long r;
    asm("mov.b64 %0, {%1, %1};" : "=l"(r) : "f"(v));
    return r;
}
__device__ __forceinline__ void ffma2_(unsigned long long& c, unsigned long long a,
                                       unsigned long long b) {
    asm("fma.rn.f32x2 %0, %1, %2, %0;" : "+l"(c) : "l"(a), "l"(b));
}

// ---------------- warp-MMA helpers (base ISA: sm_80+, compiles on sm_103) -------------
__device__ __forceinline__ uint32_t smem_u32_(const void* p) {
    uint32_t a;
    asm("{ .reg .u64 t; cvta.to.shared.u64 t, %1; cvt.u32.u64 %0, t; }" : "=r"(a) : "l"(p));
    return a;
}
__device__ __forceinline__ void ldmx4_(uint32_t& r0, uint32_t& r1, uint32_t& r2,
                                       uint32_t& r3, uint32_t addr) {
    asm volatile("ldmatrix.sync.aligned.m8n8.x4.shared.b16 {%0,%1,%2,%3}, [%4];"
                 : "=r"(r0), "=r"(r1), "=r"(r2), "=r"(r3) : "r"(addr));
}
__device__ __forceinline__ void mma16816_(float* c, const uint32_t* a, uint32_t b0,
                                          uint32_t b1) {
    asm volatile(
        "mma.sync.aligned.m16n8k16.row.col.f32.bf16.bf16.f32 "
        "{%0,%1,%2,%3}, {%4,%5,%6,%7}, {%8,%9}, {%0,%1,%2,%3};"
        : "+f"(c[0]), "+f"(c[1]), "+f"(c[2]), "+f"(c[3])
        : "r"(a[0]), "r"(a[1]), "r"(a[2]), "r"(a[3]), "r"(b0), "r"(b1));
}
__device__ __forceinline__ void bf16split_(float v, unsigned& h, unsigned& l) {
    __nv_bfloat16 hb = __float2bfloat16_rn(v);
    __nv_bfloat16 lb = __float2bfloat16_rn(v - __bfloat162float(hb));
    h = __bfloat16_as_ushort(hb); l = __bfloat16_as_ushort(lb);
}

// ---------------- K1: layernorm over D=128, warp per row; emits bf16 hi/lo planes -----
__global__ void ln_kernel(const float* __restrict__ x,
                          const float* __restrict__ scale,
                          const float* __restrict__ bias) {
    int row = blockIdx.x * 8 + threadIdx.y;
    int lane = threadIdx.x;
    float4 v = reinterpret_cast<const float4*>(x + (size_t)row * DD)[lane];
    float s  = v.x + v.y + v.z + v.w;
    float sq = v.x*v.x + v.y*v.y + v.z*v.z + v.w*v.w;
    #pragma unroll
    for (int o = 16; o > 0; o >>= 1) {
        s  += __shfl_xor_sync(0xffffffffu, s, o);
        sq += __shfl_xor_sync(0xffffffffu, sq, o);
    }
    float mu = s * (1.0f / DD);
    float var = sq * (1.0f / DD) - mu * mu;
    float rstd = rsqrtf(var + EPSV);
    float4 sc = reinterpret_cast<const float4*>(scale)[lane];
    float4 bi = reinterpret_cast<const float4*>(bias)[lane];
    float o4[4];
    o4[0] = (v.x - mu) * rstd * sc.x + bi.x;
    o4[1] = (v.y - mu) * rstd * sc.y + bi.y;
    o4[2] = (v.z - mu) * rstd * sc.z + bi.z;
    o4[3] = (v.w - mu) * rstd * sc.w + bi.w;
    unsigned h[4], l[4];
    #pragma unroll
    for (int u = 0; u < 4; u++) bf16split_(o4[u], h[u], l[u]);
    __nv_bfloat16* XH = reinterpret_cast<__nv_bfloat16*>(g_xn);
    __nv_bfloat16* XL = XH + (size_t)PP * DD;
    size_t base = (size_t)row * DD + lane * 4;
    *reinterpret_cast<uint2*>(&XH[base]) = make_uint2(h[0] | (h[1] << 16), h[2] | (h[3] << 16));
    *reinterpret_cast<uint2*>(&XL[base]) = make_uint2(l[0] | (l[1] << 16), l[2] | (l[3] << 16));
}

// ---------------- split_w: W[k][h] f32 -> WT[h][k] bf16 hi/lo, all 5 matrices ----------
__global__ __launch_bounds__(256) void split_w(
    const float* __restrict__ Wl, const float* __restrict__ Wr,
    const float* __restrict__ Wlg, const float* __restrict__ Wrg,
    const float* __restrict__ Wog) {
    const float* Ws[5] = {Wl, Wr, Wlg, Wrg, Wog};
    int m = blockIdx.x;
    const float* W = Ws[m];
    __shared__ float t[32][33];
    int tx = threadIdx.x & 31, ty = threadIdx.x >> 5;   // ty 0..7
    for (int bk = 0; bk < 4; bk++)
        for (int bh = 0; bh < 4; bh++) {
            __syncthreads();
            for (int r = ty; r < 32; r += 8)
                t[r][tx] = W[(bk*32 + r) * HH + bh*32 + tx];
            __syncthreads();
            for (int hr = ty; hr < 32; hr += 8) {
                float v = t[tx][hr];               // = W[bk*32+tx][bh*32+hr]
                unsigned hb, lb;
                bf16split_(v, hb, lb);
                size_t o = (size_t)m * DD * HH + (size_t)(bh*32 + hr) * DD + bk*32 + tx;
                g_WH[o] = __ushort_as_bfloat16((unsigned short)hb);
                g_WL[o] = __ushort_as_bfloat16((unsigned short)lb);
            }
        }
}

// ---------------- K2: proj on tensor cores (bf16 hi/lo, fused mask/sigmoid) -----------
// CTA: 128 p-rows x 64 h-cols; grid.z group: 0=(Wl,Wlg)->leftT, 1=(Wr,Wrg)->rightT,
// 2=(Wog)->ogT. 8 warps: wm(4) x wh(2), warp tile 32p x 32h, both matrices.
#define PM_PITCH 40
__global__ __launch_bounds__(256, 2) void proj_mma(
    const float* __restrict__ src_mask,
    const float* __restrict__ bl,  const float* __restrict__ br,
    const float* __restrict__ blg, const float* __restrict__ brg,
    const float* __restrict__ bog)
{
    __shared__ __align__(16) char sm_[40960];
    __nv_bfloat16* sXH = reinterpret_cast<__nv_bfloat16*>(sm_);
    __nv_bfloat16* sXL = sXH + 128 * PM_PITCH;
    __nv_bfloat16* sW  = sXL + 128 * PM_PITCH;     // [pm=mat*2+plane][64*PM_PITCH]
    uint32_t bXH = smem_u32_(sXH), bXL = smem_u32_(sXL), bW = smem_u32_(sW);

    int tid = threadIdx.x, wid = tid >> 5, lane = tid & 31;
    int wm = wid & 3, wh = wid >> 2;
    int p0 = blockIdx.x * 128, h0 = blockIdx.y * 64, grp = blockIdx.z;
    int m0 = (grp == 2) ? 4 : grp;
    int m1 = (grp == 2) ? 4 : grp + 2;

    const __nv_bfloat16* XH = reinterpret_cast<const __nv_bfloat16*>(g_xn);
    const __nv_bfloat16* XL = XH + (size_t)PP * DD;

    float acc[2][2][4][4] = {};   // [mat][mt][nt][4]

    for (int kk = 0; kk < DD; kk += 32) {
        __syncthreads();
        // X planes: 128 rows x 32 k each
        #pragma unroll
        for (int it = 0; it < 2; it++) {
            int idx = tid + it * 256;
            int r = idx >> 2, sg = idx & 3;
            size_t gg = (size_t)(p0 + r) * DD + kk + sg * 8;
            uint32_t so = (uint32_t)(r * PM_PITCH + sg * 8) * 2;
            *reinterpret_cast<uint4*>((char*)sXH + so) = *reinterpret_cast<const uint4*>(&XH[gg]);
            *reinterpret_cast<uint4*>((char*)sXL + so) = *reinterpret_cast<const uint4*>(&XL[gg]);
        }
        // W planes: 4 x (64 rows x 32 k)
        #pragma unroll
        for (int it = 0; it < 4; it++) {
            int idx = tid + it * 256;
            int pm = idx >> 8, rr2 = (idx >> 2) & 63, sg = idx & 3;
            int mat = pm >> 1, pl = pm & 1;
            int mg = mat ? m1 : m0;
            const __nv_bfloat16* src = (pl ? g_WL : g_WH) +
                (size_t)mg * DD * HH + (size_t)(h0 + rr2) * DD + kk + sg * 8;
            uint32_t so = (uint32_t)(pm * 64 * PM_PITCH + rr2 * PM_PITCH + sg * 8) * 2;
            *reinterpret_cast<uint4*>((char*)sW + so) = *reinterpret_cast<const uint4*>(src);
        }
        __syncthreads();

        #pragma unroll
        for (int ks = 0; ks < 2; ks++) {
            int k0 = ks * 16;
            uint32_t aH[2][4], aL[2][4];
            #pragma unroll
            for (int mt = 0; mt < 2; mt++) {
                int row = wm * 32 + mt * 16 + (lane & 15);
                int col = k0 + (lane >> 4) * 8;
                uint32_t off = (uint32_t)(row * PM_PITCH + col) * 2;
                ldmx4_(aH[mt][0], aH[mt][1], aH[mt][2], aH[mt][3], bXH + off);
                ldmx4_(aL[mt][0], aL[mt][1], aL[mt][2], aL[mt][3], bXL + off);
            }
            #pragma unroll
            for (int mat = 0; mat < 2; mat++) {
                uint32_t bH[4][2], bL[4][2];
                #pragma unroll
                for (int np = 0; np < 2; np++) {
                    int g8 = lane >> 3, r8 = lane & 7;
                    int nrow = wh * 32 + np * 16 + (g8 >> 1) * 8 + r8;
                    int col = k0 + (g8 & 1) * 8;
                    uint32_t offH = (uint32_t)((mat*2 + 0) * 64 * PM_PITCH + nrow * PM_PITCH + col) * 2;
                    uint32_t offL = (uint32_t)((mat*2 + 1) * 64 * PM_PITCH + nrow * PM_PITCH + col) * 2;
                    uint32_t r0, r1, r2, r3;
                    ldmx4_(r0, r1, r2, r3, bW + offH);
                    bH[np*2][0] = r0; bH[np*2][1] = r1; bH[np*2+1][0] = r2; bH[np*2+1][1] = r3;
                    ldmx4_(r0, r1, r2, r3, bW + offL);
                    bL[np*2][0] = r0; bL[np*2][1] = r1; bL[np*2+1][0] = r2; bL[np*2+1][1] = r3;
                }
                #pragma unroll
                for (int mt = 0; mt < 2; mt++)
                    #pragma unroll
                    for (int nt = 0; nt < 4; nt++) {
                        mma16816_(acc[mat][mt][nt], aH[mt], bH[nt][0], bH[nt][1]);
                        mma16816_(acc[mat][mt][nt], aH[mt], bL[nt][0], bL[nt][1]);
                        mma16816_(acc[mat][mt][nt], aL[mt], bH[nt][0], bH[nt][1]);
                    }
            }
        }
    }

    // epilogue: combine, stage (h-major), coalesced d-major writeout
    const float* b0 = (grp == 0) ? bl : (grp == 1) ? br : bog;
    const float* b1 = (grp == 0) ? blg : brg;   // unused for grp==2
    float* dst = (grp == 0) ? g_leftT : (grp == 1) ? g_rightT : g_ogT;
    float* stage = reinterpret_cast<float*>(sm_);   // [64][132]
    __syncthreads();
    #pragma unroll
    for (int mt = 0; mt < 2; mt++) {
        int ib = wm * 32 + mt * 16 + (lane >> 2);
        int pA = p0 + ib, pB = p0 + ib + 8;
        float mA = src_mask[pA >> 9] * src_mask[pA & (NN - 1)];
        float mB = src_mask[pB >> 9] * src_mask[pB & (NN - 1)];
        #pragma unroll
        for (int nt = 0; nt < 4; nt++) {
            int jl = wh * 32 + nt * 8 + (lane & 3) * 2;
            int hg = h0 + jl;
            float v00, v01, v10, v11;
            if (grp < 2) {
                float b0a = b0[hg], b0b = b0[hg + 1], b1a = b1[hg], b1b = b1[hg + 1];
                v00 = (acc[0][mt][nt][0] + b0a) * mA * sigmoidf_(acc[1][mt][nt][0] + b1a);
                v01 = (acc[0][mt][nt][1] + b0b) * mA * sigmoidf_(acc[1][mt][nt][1] + b1b);
                v10 = (acc[0][mt][nt][2] + b0a) * mB * sigmoidf_(acc[1][mt][nt][2] + b1a);
                v11 = (acc[0][mt][nt][3] + b0b) * mB * sigmoidf_(acc[1][mt][nt][3] + b1b);
            } else {
                float b0a = b0[hg], b0b = b0[hg + 1];
                v00 = sigmoidf_(acc[0][mt][nt][0] + b0a);
                v01 = sigmoidf_(acc[0][mt][nt][1] + b0b);
                v10 = sigmoidf_(acc[0][mt][nt][2] + b0a);
                v11 = sigmoidf_(acc[0][mt][nt][3] + b0b);
            }
            stage[jl * 132 + ib]           = v00;
            stage[(jl + 1) * 132 + ib]     = v01;
            stage[jl * 132 + ib + 8]       = v10;
            stage[(jl + 1) * 132 + ib + 8] = v11;
        }
    }
    __syncthreads();
    for (int idx = tid; idx < 64 * 32; idx += 256) {
        int row = idx >> 5, seg = idx & 31;
        float4 v = *reinterpret_cast<float4*>(&stage[row * 132 + seg * 4]);
        *reinterpret_cast<float4*>(&dst[(size_t)(h0 + row) * PP + p0 + seg * 4]) = v;
    }
}

// ---------------- K2b: transpose + bf16 hi/lo split (unchanged, passing) --------------
__global__ __launch_bounds__(256) void split_kernel() {
    __shared__ float tl[64][65];
    __shared__ float tr[64][65];
    int d = blockIdx.z;
    int i0 = blockIdx.x * 64, k0 = blockIdx.y * 64;
    const float* L  = g_leftT  + (size_t)d * PP;
    const float* Rm = g_rightT + (size_t)d * PP;
    int t = threadIdx.x, kr = t >> 2, sg = t & 3;
    #pragma unroll
    for (int q = 0; q < 4; q++) {
        int c = sg * 16 + q * 4;
        float4 v = *reinterpret_cast<const float4*>(&L[(size_t)(k0 + kr) * NN + i0 + c]);
        tl[kr][c] = v.x; tl[kr][c+1] = v.y; tl[kr][c+2] = v.z; tl[kr][c+3] = v.w;
        float4 w = *reinterpret_cast<const float4*>(&Rm[(size_t)(k0 + kr) * NN + i0 + c]);
        tr[kr][c] = w.x; tr[kr][c+1] = w.y; tr[kr][c+2] = w.z; tr[kr][c+3] = w.w;
    }
    __syncthreads();
    int ii = kr;
    #pragma unroll
    for (int q = 0; q < 4; q++) {
        int kk = sg * 16 + q * 4;
        size_t base = (size_t)d * PP + (size_t)(i0 + ii) * NN + k0 + kk;
        float lv[4], rv[4];
        #pragma unroll
        for (int u = 0; u < 4; u++) { lv[u] = tl[kk + u][ii]; rv[u] = tr[kk + u][ii]; }
        unsigned h[4], l[4];
        #pragma unroll
        for (int u = 0; u < 4; u++) bf16split_(lv[u], h[u], l[u]);
        uint2 lh = make_uint2(h[0] | (h[1] << 16), h[2] | (h[3] << 16));
        uint2 ll = make_uint2(l[0] | (l[1] << 16), l[2] | (l[3] << 16));
        #pragma unroll
        for (int u = 0; u < 4; u++) bf16split_(rv[u], h[u], l[u]);
        uint2 rh = make_uint2(h[0] | (h[1] << 16), h[2] | (h[3] << 16));
        uint2 rl = make_uint2(l[0] | (l[1] << 16), l[2] | (l[3] << 16));
        *reinterpret_cast<uint2*>(&g_AH[base]) = lh;
        *reinterpret_cast<uint2*>(&g_AL[base]) = ll;
        *reinterpret_cast<uint2*>(&g_BH[base]) = rh;
        *reinterpret_cast<uint2*>(&g_BL[base]) = rl;
    }
}

// ---------------- K3: triangle einsum via mma.sync (now 2 CTAs/SM) ---------------------
#define EPITCH 40
__global__ __launch_bounds__(256, 2) void einsum_mma() {
    __shared__ __align__(16) __nv_bfloat16 sAH[128 * EPITCH];
    __shared__ __align__(16) __nv_bfloat16 sAL[128 * EPITCH];
    __shared__ __align__(16) __nv_bfloat16 sBH[128 * EPITCH];
    __shared__ __align__(16) __nv_bfloat16 sBL[128 * EPITCH];
    int tid = threadIdx.x, wid = tid >> 5, lane = tid & 31;
    int wm = wid & 3, wn = wid >> 2;
    int j0 = blockIdx.x * 128, i0 = blockIdx.y * 128, d = blockIdx.z;

    const __nv_bfloat16* pAH = g_AH + (size_t)d * PP;
    const __nv_bfloat16* pAL = g_AL + (size_t)d * PP;
    const __nv_bfloat16* pBH = g_BH + (size_t)d * PP;
    const __nv_bfloat16* pBL = g_BL + (size_t)d * PP;

    uint32_t bAH = smem_u32_(sAH), bAL = smem_u32_(sAL);
    uint32_t bBH = smem_u32_(sBH), bBL = smem_u32_(sBL);

    float acc[2][8][4] = {};

    for (int kk = 0; kk < NN; kk += 32) {
        __syncthreads();
        #pragma unroll
        for (int it = 0; it < 2; it++) {
            int idx = tid + it * 256;
            int r = idx >> 2, sg = idx & 3;
            uint32_t so = (uint32_t)(r * EPITCH + sg * 8) * 2;
            size_t ga = (size_t)(i0 + r) * NN + kk + sg * 8;
            size_t gb = (size_t)(j0 + r) * NN + kk + sg * 8;
            *reinterpret_cast<uint4*>((char*)sAH + so) = *reinterpret_cast<const uint4*>(pAH + ga);
            *reinterpret_cast<uint4*>((char*)sAL + so) = *reinterpret_cast<const uint4*>(pAL + ga);
            *reinterpret_cast<uint4*>((char*)sBH + so) = *reinterpret_cast<const uint4*>(pBH + gb);
            *reinterpret_cast<uint4*>((char*)sBL + so) = *reinterpret_cast<const uint4*>(pBL + gb);
        }
        __syncthreads();

        #pragma unroll
        for (int ks = 0; ks < 2; ks++) {
            int k0 = ks * 16;
            uint32_t aH[2][4], aL[2][4];
            #pragma unroll
            for (int mt = 0; mt < 2; mt++) {
                int row = wm * 32 + mt * 16 + (lane & 15);
                int col = k0 + (lane >> 4) * 8;
                uint32_t off = (uint32_t)(row * EPITCH + col) * 2;
                ldmx4_(aH[mt][0], aH[mt][1], aH[mt][2], aH[mt][3], bAH + off);
                ldmx4_(aL[mt][0], aL[mt][1], aL[mt][2], aL[mt][3], bAL + off);
            }
            uint32_t bH[8][2], bL[8][2];
            #pragma unroll
            for (int np = 0; np < 4; np++) {
                int g8 = lane >> 3, r8 = lane & 7;
                int nrow = wn * 64 + np * 16 + (g8 >> 1) * 8 + r8;
                int col = k0 + (g8 & 1) * 8;
                uint32_t off = (uint32_t)(nrow * EPITCH + col) * 2;
                uint32_t r0, r1, r2, r3;
                ldmx4_(r0, r1, r2, r3, bBH + off);
                bH[np*2][0] = r0; bH[np*2][1] = r1; bH[np*2+1][0] = r2; bH[np*2+1][1] = r3;
                ldmx4_(r0, r1, r2, r3, bBL + off);
                bL[np*2][0] = r0; bL[np*2][1] = r1; bL[np*2+1][0] = r2; bL[np*2+1][1] = r3;
            }
            #pragma unroll
            for (int mt = 0; mt < 2; mt++)
                #pragma unroll
                for (int nt = 0; nt < 8; nt++) {
                    mma16816_(acc[mt][nt], aH[mt], bH[nt][0], bH[nt][1]);
                    mma16816_(acc[mt][nt], aH[mt], bL[nt][0], bL[nt][1]);
                    mma16816_(acc[mt][nt], aL[mt], bH[nt][0], bH[nt][1]);
                }
        }
    }

    float* O = g_xn + (size_t)d * PP;
    #pragma unroll
    for (int mt = 0; mt < 2; mt++) {
        int ib = i0 + wm * 32 + mt * 16 + (lane >> 2);
        #pragma unroll
        for (int nt = 0; nt < 8; nt++) {
            int jb = j0 + wn * 64 + nt * 8 + (lane & 3) * 2;
            *reinterpret_cast<float2*>(&O[(size_t)ib * NN + jb]) =
                make_float2(acc[mt][nt][0], acc[mt][nt][1]);
            *reinterpret_cast<float2*>(&O[(size_t)(ib + 8) * NN + jb]) =
                make_float2(acc[mt][nt][2], acc[mt][nt][3]);
        }
    }
}

// ---------------- K4: out-layernorm * ogate, then @ W_out + b_out (unchanged) ----------
__global__ __launch_bounds__(256) void out_kernel(
    const float* __restrict__ onscale, const float* __restrict__ onbias,
    const float* __restrict__ Wout,    const float* __restrict__ bout,
    float* __restrict__ out)
{
    __shared__ __align__(16) float sh[128 * 68];
    __shared__ __align__(16) float wsh[16 * 132];
    __shared__ float red_s[4][64];
    __shared__ float red_q[4][64];
    int tid = threadIdx.x;
    int p0 = blockIdx.x * 64;
    const float* outT = g_xn;

    for (int t = tid; t < 128 * 64; t += 256) {
        int dd = t >> 6, r = t & 63;
        sh[dd*68 + r] = outT[(size_t)dd * PP + p0 + r];
    }
    __syncthreads();

    int r = tid & 63, q = tid >> 6;
    float s = 0.f, sq = 0.f;
    #pragma unroll
    for (int u = 0; u < 32; u++) {
        float v = sh[(q*32 + u)*68 + r];
        s += v; sq += v*v;
    }
    red_s[q][r] = s; red_q[q][r] = sq;
    __syncthreads();
    float st  = red_s[0][r] + red_s[1][r] + red_s[2][r] + red_s[3][r];
    float sqt = red_q[0][r] + red_q[1][r] + red_q[2][r] + red_q[3][r];
    float mu = st * (1.0f / HH);
    float rstd = rsqrtf(sqt * (1.0f / HH) - mu*mu + EPSV);
    #pragma unroll
    for (int u = 0; u < 32; u++) {
        int dd = q*32 + u;
        float v = sh[dd*68 + r];
        float g = g_ogT[(size_t)dd * PP + p0 + r];
        sh[dd*68 + r] = ((v - mu) * rstd * onscale[dd] + onbias[dd]) * g;
    }

    int tx = tid & 15, ty = tid >> 4;
    unsigned long long acc2[4][4] = {};
    int lc = tid & 127, lk2 = tid >> 7;
    for (int kk = 0; kk < 128; kk += 16) {
        __syncthreads();
        #pragma unroll
        for (int qq = 0; qq < 8; qq++)
            wsh[(lk2 + qq*2)*132 + lc] = Wout[(size_t)(kk + lk2 + qq*2) * DD + lc];
        __syncthreads();
        #pragma unroll
        for (int k = 0; k < 16; k++) {
            float4 a = *reinterpret_cast<const float4*>(&sh[(kk + k)*68 + tx*4]);
            unsigned long long ap[4] = {pack2_(a.x), pack2_(a.y), pack2_(a.z), pack2_(a.w)};
            ulonglong2 w01 = *reinterpret_cast<const ulonglong2*>(&wsh[k*132 + ty*8]);
            ulonglong2 w23 = *reinterpret_cast<const ulonglong2*>(&wsh[k*132 + ty*8 + 4]);
            unsigned long long wp[4] = {w01.x, w01.y, w23.x, w23.y};
            #pragma unroll
            for (int rr = 0; rr < 4; rr++)
                #pragma unroll
                for (int cp = 0; cp < 4; cp++)
                    ffma2_(acc2[rr][cp], ap[rr], wp[cp]);
        }
    }
    float bb[8];
    *reinterpret_cast<float4*>(&bb[0]) = *reinterpret_cast<const float4*>(&bout[ty*8]);
    *reinterpret_cast<float4*>(&bb[4]) = *reinterpret_cast<const float4*>(&bout[ty*8 + 4]);
    #pragma unroll
    for (int rr = 0; rr < 4; rr++) {
        size_t base = (size_t)(p0 + tx*4 + rr) * DD + ty*8;
        const float* af = reinterpret_cast<const float*>(acc2[rr]);
        *reinterpret_cast<float4*>(&out[base]) =
            make_float4(af[0] + bb[0], af[1] + bb[1], af[2] + bb[2], af[3] + bb[3]);
        *reinterpret_cast<float4*>(&out[base + 4]) =
            make_float4(af[4] + bb[4], af[5] + bb[5], af[6] + bb[6], af[7] + bb[7]);
    }
}

// ---------------- launch ----------------
extern "C" void kernel_launch(void* const* d_in, const int* in_sizes, int n_in,
                              void* d_out, int out_size) {
    const float* x        = (const float*)d_in[0];
    const float* src_mask = (const float*)d_in[1];
    const float* nscale   = (const float*)d_in[2];
    const float* nbias    = (const float*)d_in[3];
    const float* Wl       = (const float*)d_in[4];
    const float* bl       = (const float*)d_in[5];
    const float* Wr       = (const float*)d_in[6];
    const float* br       = (const float*)d_in[7];
    const float* Wlg      = (const float*)d_in[8];
    const float* blg      = (const float*)d_in[9];
    const float* Wrg      = (const float*)d_in[10];
    const float* brg      = (const float*)d_in[11];
    const float* Wog      = (const float*)d_in[12];
    const float* bog      = (const float*)d_in[13];
    const float* onscale  = (const float*)d_in[14];
    const float* onbias   = (const float*)d_in[15];
    const float* Wout     = (const float*)d_in[16];
    const float* bout     = (const float*)d_in[17];
    float* out = (float*)d_out;

    ln_kernel<<<PP / 8, dim3(32, 8)>>>(x, nscale, nbias);
    split_w<<<5, 256>>>(Wl, Wr, Wlg, Wrg, Wog);
    proj_mma<<<dim3(PP / 128, 2, 3), 256>>>(src_mask, bl, br, blg, brg, bog);
    split_kernel<<<dim3(NN / 64, NN / 64, HH), 256>>>();
    einsum_mma<<<dim3(NN / 128, NN / 128, HH), 256>>>();
    out_kernel<<<PP / 64, 256>>>(onscale, onbias, Wout, bout, out);
}

// round 15
// speedup vs baseline: 1.7688x; 1.1562x over previous
#include <cuda_runtime.h>
#include <cuda_bf16.h>
#include <cstdint>

#define NN 512
#define DD 128
#define HH 128
#define PP (NN*NN)
#define EPSV 1e-6f

// ---------------- scratch (static device allocations; no cudaMalloc) ----------------
// Sequence: K1(ln) writes XH/XL (aliased in g_xn) -> split_w writes g_WH/g_WL ->
// K2(proj_mma) reads XH/XL + W planes, writes AH/AL/BH/BL ([d][k][i] bf16) + ogT (f32)
// -> K3(einsum_mma) reads planes via ldmatrix.trans, writes g_xn (f32 outT; XH/XL dead)
// -> K4 reads g_xn + ogT.
__device__ float g_xn[(size_t)PP * DD];      // ln: bf16 XH|XL planes; einsum: f32 outT
__device__ float g_ogT[(size_t)HH * PP];     // [d][p]
// bf16 split planes, layout [d][k*N+i] (= [d][p], K-as-rows)
__device__ __nv_bfloat16 g_AH[(size_t)HH * PP];
__device__ __nv_bfloat16 g_AL[(size_t)HH * PP];
__device__ __nv_bfloat16 g_BH[(size_t)HH * PP];
__device__ __nv_bfloat16 g_BL[(size_t)HH * PP];
// weight planes, K-major transposed: [m][h][k], m: 0=Wl 1=Wr 2=Wlg 3=Wrg 4=Wog
__device__ __nv_bfloat16 g_WH[5 * DD * HH];
__device__ __nv_bfloat16 g_WL[5 * DD * HH];

__device__ __forceinline__ float sigmoidf_(float x) {
    return 1.0f / (1.0f + expf(-x));
}

// ---------------- packed f32x2 FMA ----------------
__device__ __forceinline__ unsigned long long pack2_(float v) {
    unsigned long long r;
    asm("mov.b64 %0, {%1, %1};" : "=l"(r) : "f"(v));
    return r;
}
__device__ __forceinline__ void ffma2_(unsigned long long& c, unsigned long long a,
                                       unsigned long long b) {
    asm("fma.rn.f32x2 %0, %1, %2, %0;" : "+l"(c) : "l"(a), "l"(b));
}

// ---------------- warp-MMA helpers (base ISA) ----------------
__device__ __forceinline__ uint32_t smem_u32_(const void* p) {
    uint32_t a;
    asm("{ .reg .u64 t; cvta.to.shared.u64 t, %1; cvt.u32.u64 %0, t; }" : "=r"(a) : "l"(p));
    return a;
}
__device__ __forceinline__ void ldmx4_(uint32_t& r0, uint32_t& r1, uint32_t& r2,
                                       uint32_t& r3, uint32_t addr) {
    asm volatile("ldmatrix.sync.aligned.m8n8.x4.shared.b16 {%0,%1,%2,%3}, [%4];"
                 : "=r"(r0), "=r"(r1), "=r"(r2), "=r"(r3) : "r"(addr));
}
__device__ __forceinline__ void ldmx4t_(uint32_t& r0, uint32_t& r1, uint32_t& r2,
                                        uint32_t& r3, uint32_t addr) {
    asm volatile("ldmatrix.sync.aligned.m8n8.x4.trans.shared.b16 {%0,%1,%2,%3}, [%4];"
                 : "=r"(r0), "=r"(r1), "=r"(r2), "=r"(r3) : "r"(addr));
}
__device__ __forceinline__ void mma16816_(float* c, const uint32_t* a, uint32_t b0,
                                          uint32_t b1) {
    asm volatile(
        "mma.sync.aligned.m16n8k16.row.col.f32.bf16.bf16.f32 "
        "{%0,%1,%2,%3}, {%4,%5,%6,%7}, {%8,%9}, {%0,%1,%2,%3};"
        : "+f"(c[0]), "+f"(c[1]), "+f"(c[2]), "+f"(c[3])
        : "r"(a[0]), "r"(a[1]), "r"(a[2]), "r"(a[3]), "r"(b0), "r"(b1));
}
__device__ __forceinline__ void bf16split_(float v, unsigned& h, unsigned& l) {
    __nv_bfloat16 hb = __float2bfloat16_rn(v);
    __nv_bfloat16 lb = __float2bfloat16_rn(v - __bfloat162float(hb));
    h = __bfloat16_as_ushort(hb); l = __bfloat16_as_ushort(lb);
}

// ---------------- K1: layernorm over D=128, warp per row; emits bf16 hi/lo planes -----
__global__ void ln_kernel(const float* __restrict__ x,
                          const float* __restrict__ scale,
                          const float* __restrict__ bias) {
    int row = blockIdx.x * 8 + threadIdx.y;
    int lane = threadIdx.x;
    float4 v = reinterpret_cast<const float4*>(x + (size_t)row * DD)[lane];
    float s  = v.x + v.y + v.z + v.w;
    float sq = v.x*v.x + v.y*v.y + v.z*v.z + v.w*v.w;
    #pragma unroll
    for (int o = 16; o > 0; o >>= 1) {
        s  += __shfl_xor_sync(0xffffffffu, s, o);
        sq += __shfl_xor_sync(0xffffffffu, sq, o);
    }
    float mu = s * (1.0f / DD);
    float var = sq * (1.0f / DD) - mu * mu;
    float rstd = rsqrtf(var + EPSV);
    float4 sc = reinterpret_cast<const float4*>(scale)[lane];
    float4 bi = reinterpret_cast<const float4*>(bias)[lane];
    float o4[4];
    o4[0] = (v.x - mu) * rstd * sc.x + bi.x;
    o4[1] = (v.y - mu) * rstd * sc.y + bi.y;
    o4[2] = (v.z - mu) * rstd * sc.z + bi.z;
    o4[3] = (v.w - mu) * rstd * sc.w + bi.w;
    unsigned h[4], l[4];
    #pragma unroll
    for (int u = 0; u < 4; u++) bf16split_(o4[u], h[u], l[u]);
    __nv_bfloat16* XH = reinterpret_cast<__nv_bfloat16*>(g_xn);
    __nv_bfloat16* XL = XH + (size_t)PP * DD;
    size_t base = (size_t)row * DD + lane * 4;
    *reinterpret_cast<uint2*>(&XH[base]) = make_uint2(h[0] | (h[1] << 16), h[2] | (h[3] << 16));
    *reinterpret_cast<uint2*>(&XL[base]) = make_uint2(l[0] | (l[1] << 16), l[2] | (l[3] << 16));
}

// ---------------- split_w: W[k][h] f32 -> WT[h][k] bf16 hi/lo, all 5 matrices ----------
__global__ __launch_bounds__(256) void split_w(
    const float* __restrict__ Wl, const float* __restrict__ Wr,
    const float* __restrict__ Wlg, const float* __restrict__ Wrg,
    const float* __restrict__ Wog) {
    const float* Ws[5] = {Wl, Wr, Wlg, Wrg, Wog};
    int m = blockIdx.x;
    const float* W = Ws[m];
    __shared__ float t[32][33];
    int tx = threadIdx.x & 31, ty = threadIdx.x >> 5;   // ty 0..7
    for (int bk = 0; bk < 4; bk++)
        for (int bh = 0; bh < 4; bh++) {
            __syncthreads();
            for (int r = ty; r < 32; r += 8)
                t[r][tx] = W[(bk*32 + r) * HH + bh*32 + tx];
            __syncthreads();
            for (int hr = ty; hr < 32; hr += 8) {
                float v = t[tx][hr];               // = W[bk*32+tx][bh*32+hr]
                unsigned hb, lb;
                bf16split_(v, hb, lb);
                size_t o = (size_t)m * DD * HH + (size_t)(bh*32 + hr) * DD + bk*32 + tx;
                g_WH[o] = __ushort_as_bfloat16((unsigned short)hb);
                g_WL[o] = __ushort_as_bfloat16((unsigned short)lb);
            }
        }
}

// ---------------- K2: proj on tensor cores; epilogue emits bf16 hi/lo planes ----------
// CTA: 128 p-rows x 64 h-cols; grid.z group: 0=(Wl,Wlg)->AH/AL, 1=(Wr,Wrg)->BH/BL,
// 2=(Wog)->ogT (f32). 8 warps: wm(4) x wh(2), warp tile 32p x 32h.
#define PM_PITCH 40
__global__ __launch_bounds__(256, 2) void proj_mma(
    const float* __restrict__ src_mask,
    const float* __restrict__ bl,  const float* __restrict__ br,
    const float* __restrict__ blg, const float* __restrict__ brg,
    const float* __restrict__ bog)
{
    __shared__ __align__(16) char sm_[40960];
    __nv_bfloat16* sXH = reinterpret_cast<__nv_bfloat16*>(sm_);
    __nv_bfloat16* sXL = sXH + 128 * PM_PITCH;
    __nv_bfloat16* sW  = sXL + 128 * PM_PITCH;     // [pm=mat*2+plane][64*PM_PITCH]
    uint32_t bXH = smem_u32_(sXH), bXL = smem_u32_(sXL), bW = smem_u32_(sW);

    int tid = threadIdx.x, wid = tid >> 5, lane = tid & 31;
    int wm = wid & 3, wh = wid >> 2;
    int p0 = blockIdx.x * 128, h0 = blockIdx.y * 64, grp = blockIdx.z;
    int m0 = (grp == 2) ? 4 : grp;
    int m1 = (grp == 2) ? 4 : grp + 2;

    const __nv_bfloat16* XH = reinterpret_cast<const __nv_bfloat16*>(g_xn);
    const __nv_bfloat16* XL = XH + (size_t)PP * DD;

    float acc[2][2][4][4] = {};   // [mat][mt][nt][4]

    for (int kk = 0; kk < DD; kk += 32) {
        __syncthreads();
        #pragma unroll
        for (int it = 0; it < 2; it++) {
            int idx = tid + it * 256;
            int r = idx >> 2, sg = idx & 3;
            size_t gg = (size_t)(p0 + r) * DD + kk + sg * 8;
            uint32_t so = (uint32_t)(r * PM_PITCH + sg * 8) * 2;
            *reinterpret_cast<uint4*>((char*)sXH + so) = *reinterpret_cast<const uint4*>(&XH[gg]);
            *reinterpret_cast<uint4*>((char*)sXL + so) = *reinterpret_cast<const uint4*>(&XL[gg]);
        }
        #pragma unroll
        for (int it = 0; it < 4; it++) {
            int idx = tid + it * 256;
            int pm = idx >> 8, rr2 = (idx >> 2) & 63, sg = idx & 3;
            int mat = pm >> 1, pl = pm & 1;
            int mg = mat ? m1 : m0;
            const __nv_bfloat16* src = (pl ? g_WL : g_WH) +
                (size_t)mg * DD * HH + (size_t)(h0 + rr2) * DD + kk + sg * 8;
            uint32_t so = (uint32_t)(pm * 64 * PM_PITCH + rr2 * PM_PITCH + sg * 8) * 2;
            *reinterpret_cast<uint4*>((char*)sW + so) = *reinterpret_cast<const uint4*>(src);
        }
        __syncthreads();

        #pragma unroll
        for (int ks = 0; ks < 2; ks++) {
            int k0 = ks * 16;
            uint32_t aH[2][4], aL[2][4];
            #pragma unroll
            for (int mt = 0; mt < 2; mt++) {
                int row = wm * 32 + mt * 16 + (lane & 15);
                int col = k0 + (lane >> 4) * 8;
                uint32_t off = (uint32_t)(row * PM_PITCH + col) * 2;
                ldmx4_(aH[mt][0], aH[mt][1], aH[mt][2], aH[mt][3], bXH + off);
                ldmx4_(aL[mt][0], aL[mt][1], aL[mt][2], aL[mt][3], bXL + off);
            }
            #pragma unroll
            for (int mat = 0; mat < 2; mat++) {
                uint32_t bH[4][2], bL[4][2];
                #pragma unroll
                for (int np = 0; np < 2; np++) {
                    int g8 = lane >> 3, r8 = lane & 7;
                    int nrow = wh * 32 + np * 16 + (g8 >> 1) * 8 + r8;
                    int col = k0 + (g8 & 1) * 8;
                    uint32_t offH = (uint32_t)((mat*2 + 0) * 64 * PM_PITCH + nrow * PM_PITCH + col) * 2;
                    uint32_t offL = (uint32_t)((mat*2 + 1) * 64 * PM_PITCH + nrow * PM_PITCH + col) * 2;
                    uint32_t r0, r1, r2, r3;
                    ldmx4_(r0, r1, r2, r3, bW + offH);
                    bH[np*2][0] = r0; bH[np*2][1] = r1; bH[np*2+1][0] = r2; bH[np*2+1][1] = r3;
                    ldmx4_(r0, r1, r2, r3, bW + offL);
                    bL[np*2][0] = r0; bL[np*2][1] = r1; bL[np*2+1][0] = r2; bL[np*2+1][1] = r3;
                }
                #pragma unroll
                for (int mt = 0; mt < 2; mt++)
                    #pragma unroll
                    for (int nt = 0; nt < 4; nt++) {
                        mma16816_(acc[mat][mt][nt], aH[mt], bH[nt][0], bH[nt][1]);
                        mma16816_(acc[mat][mt][nt], aH[mt], bL[nt][0], bL[nt][1]);
                        mma16816_(acc[mat][mt][nt], aL[mt], bH[nt][0], bH[nt][1]);
                    }
            }
        }
    }

    // epilogue
    const float* b0 = (grp == 0) ? bl : (grp == 1) ? br : bog;
    const float* b1 = (grp == 0) ? blg : brg;   // unused for grp==2
    __syncthreads();
    if (grp < 2) {
        // stage packed (hi | lo<<16) u32; then coalesced bf16-plane writeout
        uint32_t* stg = reinterpret_cast<uint32_t*>(sm_);   // [64][132]
        #pragma unroll
        for (int mt = 0; mt < 2; mt++) {
            int ib = wm * 32 + mt * 16 + (lane >> 2);
            int pA = p0 + ib, pB = p0 + ib + 8;
            float mA = src_mask[pA >> 9] * src_mask[pA & (NN - 1)];
            float mB = src_mask[pB >> 9] * src_mask[pB & (NN - 1)];
            #pragma unroll
            for (int nt = 0; nt < 4; nt++) {
                int jl = wh * 32 + nt * 8 + (lane & 3) * 2;
                int hg = h0 + jl;
                float b0a = b0[hg], b0b = b0[hg + 1], b1a = b1[hg], b1b = b1[hg + 1];
                float v00 = (acc[0][mt][nt][0] + b0a) * mA * sigmoidf_(acc[1][mt][nt][0] + b1a);
                float v01 = (acc[0][mt][nt][1] + b0b) * mA * sigmoidf_(acc[1][mt][nt][1] + b1b);
                float v10 = (acc[0][mt][nt][2] + b0a) * mB * sigmoidf_(acc[1][mt][nt][2] + b1a);
                float v11 = (acc[0][mt][nt][3] + b0b) * mB * sigmoidf_(acc[1][mt][nt][3] + b1b);
                unsigned h_, l_;
                bf16split_(v00, h_, l_); stg[jl * 132 + ib]           = h_ | (l_ << 16);
                bf16split_(v01, h_, l_); stg[(jl + 1) * 132 + ib]     = h_ | (l_ << 16);
                bf16split_(v10, h_, l_); stg[jl * 132 + ib + 8]       = h_ | (l_ << 16);
                bf16split_(v11, h_, l_); stg[(jl + 1) * 132 + ib + 8] = h_ | (l_ << 16);
            }
        }
        __syncthreads();
        __nv_bfloat16* dH = (grp == 0) ? g_AH : g_BH;
        __nv_bfloat16* dL = (grp == 0) ? g_AL : g_BL;
        for (int idx = tid; idx < 64 * 32; idx += 256) {
            int row = idx >> 5, seg = idx & 31;
            uint32_t w0 = stg[row * 132 + seg*4];
            uint32_t w1 = stg[row * 132 + seg*4 + 1];
            uint32_t w2 = stg[row * 132 + seg*4 + 2];
            uint32_t w3 = stg[row * 132 + seg*4 + 3];
            uint2 hv = make_uint2((w0 & 0xffffu) | (w1 << 16), (w2 & 0xffffu) | (w3 << 16));
            uint2 lv = make_uint2((w0 >> 16) | (w1 & 0xffff0000u), (w2 >> 16) | (w3 & 0xffff0000u));
            size_t o = (size_t)(h0 + row) * PP + p0 + seg * 4;
            *reinterpret_cast<uint2*>(&dH[o]) = hv;
            *reinterpret_cast<uint2*>(&dL[o]) = lv;
        }
    } else {
        float* stage = reinterpret_cast<float*>(sm_);   // [64][132]
        #pragma unroll
        for (int mt = 0; mt < 2; mt++) {
            int ib = wm * 32 + mt * 16 + (lane >> 2);
            #pragma unroll
            for (int nt = 0; nt < 4; nt++) {
                int jl = wh * 32 + nt * 8 + (lane & 3) * 2;
                int hg = h0 + jl;
                float b0a = b0[hg], b0b = b0[hg + 1];
                stage[jl * 132 + ib]           = sigmoidf_(acc[0][mt][nt][0] + b0a);
                stage[(jl + 1) * 132 + ib]     = sigmoidf_(acc[0][mt][nt][1] + b0b);
                stage[jl * 132 + ib + 8]       = sigmoidf_(acc[0][mt][nt][2] + b0a);
                stage[(jl + 1) * 132 + ib + 8] = sigmoidf_(acc[0][mt][nt][3] + b0b);
            }
        }
        __syncthreads();
        for (int idx = tid; idx < 64 * 32; idx += 256) {
            int row = idx >> 5, seg = idx & 31;
            float4 v = *reinterpret_cast<float4*>(&stage[row * 132 + seg * 4]);
            *reinterpret_cast<float4*>(&g_ogT[(size_t)(h0 + row) * PP + p0 + seg * 4]) = v;
        }
    }
}

// ---------------- K3: triangle einsum via mma.sync; K-as-rows planes + ldmatrix.trans --
// out[d][i][j] = sum_k AH/AL[d][k][i] * BH/BL[d][k][j]
#define EPITCH 136
__global__ __launch_bounds__(256, 2) void einsum_mma() {
    __shared__ __align__(16) __nv_bfloat16 sAH[32 * EPITCH];
    __shared__ __align__(16) __nv_bfloat16 sAL[32 * EPITCH];
    __shared__ __align__(16) __nv_bfloat16 sBH[32 * EPITCH];
    __shared__ __align__(16) __nv_bfloat16 sBL[32 * EPITCH];
    int tid = threadIdx.x, wid = tid >> 5, lane = tid & 31;
    int wm = wid & 3, wn = wid >> 2;
    int j0 = blockIdx.x * 128, i0 = blockIdx.y * 128, d = blockIdx.z;

    const __nv_bfloat16* gsrc[4] = {
        g_AH + (size_t)d * PP + i0, g_AL + (size_t)d * PP + i0,
        g_BH + (size_t)d * PP + j0, g_BL + (size_t)d * PP + j0};
    char* sdst[4] = {(char*)sAH, (char*)sAL, (char*)sBH, (char*)sBL};

    uint32_t bAH = smem_u32_(sAH), bAL = smem_u32_(sAL);
    uint32_t bBH = smem_u32_(sBH), bBL = smem_u32_(sBL);

    float acc[2][8][4] = {};

    for (int kk = 0; kk < NN; kk += 32) {
        __syncthreads();
        // 4 planes x 32 k-rows x 128 cols; rows contiguous in global
        #pragma unroll
        for (int pl = 0; pl < 4; pl++) {
            #pragma unroll
            for (int half = 0; half < 2; half++) {
                int rem = half * 256 + tid;
                int r = rem >> 4, sg = rem & 15;
                uint32_t so = (uint32_t)(r * EPITCH + sg * 8) * 2;
                *reinterpret_cast<uint4*>(sdst[pl] + so) =
                    *reinterpret_cast<const uint4*>(gsrc[pl] + (size_t)(kk + r) * NN + sg * 8);
            }
        }
        __syncthreads();

        #pragma unroll
        for (int ks = 0; ks < 2; ks++) {
            int k0 = ks * 16;
            // A frags via trans: tiles (m0,k0),(m8,k0),(m0,k8),(m8,k8)
            uint32_t aH[2][4], aL[2][4];
            #pragma unroll
            for (int mt = 0; mt < 2; mt++) {
                int m0 = wm * 32 + mt * 16;
                int row = k0 + ((lane >> 4) << 3) + (lane & 7);
                int col = m0 + (((lane >> 3) & 1) << 3);
                uint32_t off = (uint32_t)(row * EPITCH + col) * 2;
                ldmx4t_(aH[mt][0], aH[mt][1], aH[mt][2], aH[mt][3], bAH + off);
                ldmx4t_(aL[mt][0], aL[mt][1], aL[mt][2], aL[mt][3], bAL + off);
            }
            // B frags via trans: tiles (n0,k0),(n0,k8),(n8,k0),(n8,k8)
            uint32_t bH[8][2], bL[8][2];
            #pragma unroll
            for (int np = 0; np < 4; np++) {
                int n0 = wn * 64 + np * 16;
                int row = k0 + (((lane >> 3) & 1) << 3) + (lane & 7);
                int col = n0 + ((lane >> 4) << 3);
                uint32_t off = (uint32_t)(row * EPITCH + col) * 2;
                uint32_t r0, r1, r2, r3;
                ldmx4t_(r0, r1, r2, r3, bBH + off);
                bH[np*2][0] = r0; bH[np*2][1] = r1; bH[np*2+1][0] = r2; bH[np*2+1][1] = r3;
                ldmx4t_(r0, r1, r2, r3, bBL + off);
                bL[np*2][0] = r0; bL[np*2][1] = r1; bL[np*2+1][0] = r2; bL[np*2+1][1] = r3;
            }
            #pragma unroll
            for (int mt = 0; mt < 2; mt++)
                #pragma unroll
                for (int nt = 0; nt < 8; nt++) {
                    mma16816_(acc[mt][nt], aH[mt], bH[nt][0], bH[nt][1]);
                    mma16816_(acc[mt][nt], aH[mt], bL[nt][0], bL[nt][1]);
                    mma16816_(acc[mt][nt], aL[mt], bH[nt][0], bH[nt][1]);
                }
        }
    }

    float* O = g_xn + (size_t)d * PP;
    #pragma unroll
    for (int mt = 0; mt < 2; mt++) {
        int ib = i0 + wm * 32 + mt * 16 + (lane >> 2);
        #pragma unroll
        for (int nt = 0; nt < 8; nt++) {
            int jb = j0 + wn * 64 + nt * 8 + (lane & 3) * 2;
            *reinterpret_cast<float2*>(&O[(size_t)ib * NN + jb]) =
                make_float2(acc[mt][nt][0], acc[mt][nt][1]);
            *reinterpret_cast<float2*>(&O[(size_t)(ib + 8) * NN + jb]) =
                make_float2(acc[mt][nt][2], acc[mt][nt][3]);
        }
    }
}

// ---------------- K4: out-layernorm * ogate, then @ W_out + b_out (unchanged) ----------
__global__ __launch_bounds__(256) void out_kernel(
    const float* __restrict__ onscale, const float* __restrict__ onbias,
    const float* __restrict__ Wout,    const float* __restrict__ bout,
    float* __restrict__ out)
{
    __shared__ __align__(16) float sh[128 * 68];
    __shared__ __align__(16) float wsh[16 * 132];
    __shared__ float red_s[4][64];
    __shared__ float red_q[4][64];
    int tid = threadIdx.x;
    int p0 = blockIdx.x * 64;
    const float* outT = g_xn;

    for (int t = tid; t < 128 * 64; t += 256) {
        int dd = t >> 6, r = t & 63;
        sh[dd*68 + r] = outT[(size_t)dd * PP + p0 + r];
    }
    __syncthreads();

    int r = tid & 63, q = tid >> 6;
    float s = 0.f, sq = 0.f;
    #pragma unroll
    for (int u = 0; u < 32; u++) {
        float v = sh[(q*32 + u)*68 + r];
        s += v; sq += v*v;
    }
    red_s[q][r] = s; red_q[q][r] = sq;
    __syncthreads();
    float st  = red_s[0][r] + red_s[1][r] + red_s[2][r] + red_s[3][r];
    float sqt = red_q[0][r] + red_q[1][r] + red_q[2][r] + red_q[3][r];
    float mu = st * (1.0f / HH);
    float rstd = rsqrtf(sqt * (1.0f / HH) - mu*mu + EPSV);
    #pragma unroll
    for (int u = 0; u < 32; u++) {
        int dd = q*32 + u;
        float v = sh[dd*68 + r];
        float g = g_ogT[(size_t)dd * PP + p0 + r];
        sh[dd*68 + r] = ((v - mu) * rstd * onscale[dd] + onbias[dd]) * g;
    }

    int tx = tid & 15, ty = tid >> 4;
    unsigned long long acc2[4][4] = {};
    int lc = tid & 127, lk2 = tid >> 7;
    for (int kk = 0; kk < 128; kk += 16) {
        __syncthreads();
        #pragma unroll
        for (int qq = 0; qq < 8; qq++)
            wsh[(lk2 + qq*2)*132 + lc] = Wout[(size_t)(kk + lk2 + qq*2) * DD + lc];
        __syncthreads();
        #pragma unroll
        for (int k = 0; k < 16; k++) {
            float4 a = *reinterpret_cast<const float4*>(&sh[(kk + k)*68 + tx*4]);
            unsigned long long ap[4] = {pack2_(a.x), pack2_(a.y), pack2_(a.z), pack2_(a.w)};
            ulonglong2 w01 = *reinterpret_cast<const ulonglong2*>(&wsh[k*132 + ty*8]);
            ulonglong2 w23 = *reinterpret_cast<const ulonglong2*>(&wsh[k*132 + ty*8 + 4]);
            unsigned long long wp[4] = {w01.x, w01.y, w23.x, w23.y};
            #pragma unroll
            for (int rr = 0; rr < 4; rr++)
                #pragma unroll
                for (int cp = 0; cp < 4; cp++)
                    ffma2_(acc2[rr][cp], ap[rr], wp[cp]);
        }
    }
    float bb[8];
    *reinterpret_cast<float4*>(&bb[0]) = *reinterpret_cast<const float4*>(&bout[ty*8]);
    *reinterpret_cast<float4*>(&bb[4]) = *reinterpret_cast<const float4*>(&bout[ty*8 + 4]);
    #pragma unroll
    for (int rr = 0; rr < 4; rr++) {
        size_t base = (size_t)(p0 + tx*4 + rr) * DD + ty*8;
        const float* af = reinterpret_cast<const float*>(acc2[rr]);
        *reinterpret_cast<float4*>(&out[base]) =
            make_float4(af[0] + bb[0], af[1] + bb[1], af[2] + bb[2], af[3] + bb[3]);
        *reinterpret_cast<float4*>(&out[base + 4]) =
            make_float4(af[4] + bb[4], af[5] + bb[5], af[6] + bb[6], af[7] + bb[7]);
    }
}

// ---------------- launch ----------------
extern "C" void kernel_launch(void* const* d_in, const int* in_sizes, int n_in,
                              void* d_out, int out_size) {
    const float* x        = (const float*)d_in[0];
    const float* src_mask = (const float*)d_in[1];
    const float* nscale   = (const float*)d_in[2];
    const float* nbias    = (const float*)d_in[3];
    const float* Wl       = (const float*)d_in[4];
    const float* bl       = (const float*)d_in[5];
    const float* Wr       = (const float*)d_in[6];
    const float* br       = (const float*)d_in[7];
    const float* Wlg      = (const float*)d_in[8];
    const float* blg      = (const float*)d_in[9];
    const float* Wrg      = (const float*)d_in[10];
    const float* brg      = (const float*)d_in[11];
    const float* Wog      = (const float*)d_in[12];
    const float* bog      = (const float*)d_in[13];
    const float* onscale  = (const float*)d_in[14];
    const float* onbias   = (const float*)d_in[15];
    const float* Wout     = (const float*)d_in[16];
    const float* bout     = (const float*)d_in[17];
    float* out = (float*)d_out;

    ln_kernel<<<PP / 8, dim3(32, 8)>>>(x, nscale, nbias);
    split_w<<<5, 256>>>(Wl, Wr, Wlg, Wrg, Wog);
    proj_mma<<<dim3(PP / 128, 2, 3), 256>>>(src_mask, bl, br, blg, brg, bog);
    einsum_mma<<<dim3(NN / 128, NN / 128, HH), 256>>>();
    out_kernel<<<PP / 64, 256>>>(onscale, onbias, Wout, bout, out);
}